// round 1
// baseline (speedup 1.0000x reference)
#include <cuda_runtime.h>
#include <cstdint>
#include <cstddef>

#define Bn 8
#define Tn 2048
#define Dn 1024
#define HSn 64
#define TQ 8
#define VT 32

// Scratch (allocation-free rule: __device__ globals)
__device__ float g_q[(size_t)Bn * Tn * HSn];      // [b][t][h]
__device__ float g_k8t[(size_t)Bn * HSn * Tn];    // [b][h][t], pre-scaled by 8 (= sqrt(HS))
__device__ float g_v[(size_t)Bn * Tn * HSn];      // [b][t][h]

// ---------------------------------------------------------------------------
// K1: fused QKV projection.  [16384 x 1024] @ [1024 x 192] fp32, smem-tiled.
// Block: 32 tokens x 192 cols, 256 threads, micro-tile 4 tok x 6 cols.
// cols 0..63 -> k (Wk), 64..127 -> q (Wq), 128..191 -> v (Wv)
// ---------------------------------------------------------------------------
__global__ __launch_bounds__(256, 3)
void proj_kernel(const float* __restrict__ x,
                 const float* __restrict__ Wk, const float* __restrict__ bk,
                 const float* __restrict__ Wq, const float* __restrict__ bq,
                 const float* __restrict__ Wv, const float* __restrict__ bv)
{
    __shared__ float xs[32][65];    // [tok][k], padded
    __shared__ float ws[64][193];   // [k][col], padded

    const int tid  = threadIdx.x;
    const int tok0 = blockIdx.x * 32;
    const int cl   = tid & 31;          // column lane
    const int tr   = (tid >> 5) << 2;   // 4 tokens per thread

    float acc[4][6];
#pragma unroll
    for (int i = 0; i < 4; ++i)
#pragma unroll
        for (int j = 0; j < 6; ++j) acc[i][j] = 0.f;

    for (int k0 = 0; k0 < Dn; k0 += 64) {
        __syncthreads();
        // stage x tile: 32 tok x 64 k (coalesced read, conflict-free write)
        for (int idx = tid; idx < 32 * 64; idx += 256) {
            int k = idx & 63, tk = idx >> 6;
            xs[tk][k] = x[(size_t)(tok0 + tk) * Dn + k0 + k];
        }
        // stage W tile: 64 k x 192 cols
        for (int idx = tid; idx < 192 * 64; idx += 256) {
            int k = idx & 63, col = idx >> 6;
            const float* Wsrc = (col < 64) ? Wk : ((col < 128) ? Wq : Wv);
            ws[k][col] = Wsrc[(size_t)(col & 63) * Dn + k0 + k];
        }
        __syncthreads();

#pragma unroll 8
        for (int k = 0; k < 64; ++k) {
            float xv0 = xs[tr + 0][k];
            float xv1 = xs[tr + 1][k];
            float xv2 = xs[tr + 2][k];
            float xv3 = xs[tr + 3][k];
#pragma unroll
            for (int j = 0; j < 6; ++j) {
                float wv = ws[k][cl + 32 * j];
                acc[0][j] = fmaf(xv0, wv, acc[0][j]);
                acc[1][j] = fmaf(xv1, wv, acc[1][j]);
                acc[2][j] = fmaf(xv2, wv, acc[2][j]);
                acc[3][j] = fmaf(xv3, wv, acc[3][j]);
            }
        }
    }

#pragma unroll
    for (int i = 0; i < 4; ++i) {
        int tokg = tok0 + tr + i;
        int b = tokg >> 11;            // tokg / 2048
        int t = tokg & (Tn - 1);
#pragma unroll
        for (int j = 0; j < 6; ++j) {
            int col = cl + 32 * j;
            int h = col & 63;
            if (col < 64) {
                float r = acc[i][j] + bk[h];
                g_k8t[((size_t)b * HSn + h) * Tn + t] = 8.0f * r;  // fold sqrt(HS)=8
            } else if (col < 128) {
                g_q[(size_t)tokg * HSn + h] = acc[i][j] + bq[h];
            } else {
                g_v[(size_t)tokg * HSn + h] = acc[i][j] + bv[h];
            }
        }
    }
}

// ---------------------------------------------------------------------------
// K2: fused attention with rel-pos bias, flash-style online softmax.
// Block: 8 query positions (t0..t0+7) x all 8 batches. Warp w = batch w.
// Streams v in tiles of 32; rel tile staged transposed in smem (read-once).
// s[b,t,v] = sum_h q[b,t,h] * (8*k[b,v,h] + rel[t,v,h])
// ---------------------------------------------------------------------------
#define ATTN_SMEM_FLOATS (TQ * HSn * (VT + 1) + Bn * TQ * HSn + Bn * TQ * VT)
#define ATTN_SMEM_BYTES  (ATTN_SMEM_FLOATS * 4)

__global__ __launch_bounds__(256, 2)
void attn_kernel(const float* __restrict__ rel, float* __restrict__ out)
{
    extern __shared__ float sm[];
    float* srelT = sm;                              // [TQ][64][VT+1]  (t,h,v) padded
    float* sq    = srelT + TQ * HSn * (VT + 1);     // [B][TQ][HS]
    float* sp    = sq + Bn * TQ * HSn;              // [B][TQ][VT]

    const int tid  = threadIdx.x;
    const int w    = tid >> 5;     // batch index
    const int lane = tid & 31;
    const int t0   = blockIdx.x * TQ;

    // stage q for this t-block, all batches: [b][tt][h]
    for (int idx = tid; idx < Bn * TQ * HSn; idx += 256) {
        int h  = idx & 63;
        int tt = (idx >> 6) & (TQ - 1);
        int b  = idx >> 9;
        sq[idx] = g_q[((size_t)b * Tn + t0 + tt) * HSn + h];
    }
    // (first __syncthreads in the tile loop publishes sq)

    float m[TQ], l[TQ], oa0[TQ], oa1[TQ];
#pragma unroll
    for (int tt = 0; tt < TQ; ++tt) {
        m[tt] = -1e30f; l[tt] = 0.f; oa0[tt] = 0.f; oa1[tt] = 0.f;
    }

    const float* k8b = g_k8t + (size_t)w * HSn * Tn;   // [h][t]
    const float* vb  = g_v   + (size_t)w * Tn * HSn;   // [t][h]
    const float* qb  = sq + w * TQ * HSn;

    for (int v0 = 0; v0 < Tn; v0 += VT) {
        __syncthreads();
        // stage rel[t0..t0+7][v0..v0+31][0..63] transposed -> srelT[t][h][v]
        for (int idx = tid; idx < TQ * VT * HSn; idx += 256) {
            int h  = idx & 63;
            int v  = (idx >> 6) & (VT - 1);
            int tt = idx >> 11;
            srelT[(tt * HSn + h) * (VT + 1) + v] =
                rel[((size_t)(t0 + tt) * Tn + v0 + v) * HSn + h];
        }
        __syncthreads();

        // ---- Phase A: scores. lane's key index = v0 + lane ----
        float s[TQ];
#pragma unroll
        for (int tt = 0; tt < TQ; ++tt) s[tt] = 0.f;

#pragma unroll 4
        for (int h = 0; h < HSn; ++h) {
            float k8 = __ldg(k8b + (size_t)h * Tn + v0 + lane);
            const float* sr = srelT + h * (VT + 1) + lane;
#pragma unroll
            for (int tt = 0; tt < TQ; ++tt) {
                float qv = qb[tt * HSn + h];                 // LDS broadcast
                float rv = sr[tt * HSn * (VT + 1)];          // conflict-free LDS
                s[tt] = fmaf(qv, k8, fmaf(qv, rv, s[tt]));
            }
        }

        // ---- Phase B: online softmax (warp owns full row) ----
#pragma unroll
        for (int tt = 0; tt < TQ; ++tt) {
            float mt = s[tt];
#pragma unroll
            for (int o = 16; o > 0; o >>= 1)
                mt = fmaxf(mt, __shfl_xor_sync(0xffffffffu, mt, o));
            float mn = fmaxf(m[tt], mt);
            float sc = __expf(m[tt] - mn);
            float p  = __expf(s[tt] - mn);
            m[tt] = mn;
            l[tt] = l[tt] * sc + p;
            oa0[tt] *= sc; oa1[tt] *= sc;
            sp[(w * TQ + tt) * VT + lane] = p;
        }
        __syncwarp();

        // ---- Phase C: PV. lanes over h (h = lane, lane+32) ----
#pragma unroll 4
        for (int v = 0; v < VT; ++v) {
            const float* vr = vb + (size_t)(v0 + v) * HSn;
            float ve0 = vr[lane];
            float ve1 = vr[lane + 32];
            const float* pp = sp + w * TQ * VT + v;
#pragma unroll
            for (int tt = 0; tt < TQ; ++tt) {
                float p = pp[tt * VT];                       // LDS broadcast
                oa0[tt] = fmaf(p, ve0, oa0[tt]);
                oa1[tt] = fmaf(p, ve1, oa1[tt]);
            }
        }
        __syncwarp();
    }

    // ---- finalize: reduce l across lanes, normalize, write out ----
#pragma unroll
    for (int tt = 0; tt < TQ; ++tt) {
        float lt = l[tt];
#pragma unroll
        for (int o = 16; o > 0; o >>= 1)
            lt += __shfl_xor_sync(0xffffffffu, lt, o);
        float inv = 1.0f / lt;
        size_t o0 = ((size_t)w * Tn + t0 + tt) * HSn;
        out[o0 + lane]      = oa0[tt] * inv;
        out[o0 + lane + 32] = oa1[tt] * inv;
    }
}

// ---------------------------------------------------------------------------
extern "C" void kernel_launch(void* const* d_in, const int* in_sizes, int n_in,
                              void* d_out, int out_size)
{
    const float* x   = (const float*)d_in[0];
    const float* Wk  = (const float*)d_in[1];
    const float* bk  = (const float*)d_in[2];
    const float* Wq  = (const float*)d_in[3];
    const float* bq  = (const float*)d_in[4];
    const float* Wv  = (const float*)d_in[5];
    const float* bv  = (const float*)d_in[6];
    const float* rel = (const float*)d_in[7];
    float* out = (float*)d_out;

    cudaFuncSetAttribute(attn_kernel,
                         cudaFuncAttributeMaxDynamicSharedMemorySize,
                         ATTN_SMEM_BYTES);

    proj_kernel<<<(Bn * Tn) / 32, 256>>>(x, Wk, bk, Wq, bq, Wv, bv);
    attn_kernel<<<Tn / TQ, 256, ATTN_SMEM_BYTES>>>(rel, out);
}

// round 2
// speedup vs baseline: 1.0536x; 1.0536x over previous
#include <cuda_runtime.h>
#include <cstdint>
#include <cstddef>

#define Bn 8
#define Tn 2048
#define Dn 1024
#define HSn 64
#define TQ 8
#define VT 32
#define SPLIT 2
#define VLEN (Tn / SPLIT)

// Scratch (allocation-free rule: __device__ globals)
__device__ float g_q[(size_t)Bn * Tn * HSn];      // [b][t][h]
__device__ float g_k8t[(size_t)Bn * HSn * Tn];    // [b][h][t], pre-scaled by 8
__device__ float g_v[(size_t)Bn * Tn * HSn];      // [b][t][h]
__device__ float g_po[SPLIT][(size_t)Bn * Tn * HSn];  // unnormalized partial O
__device__ float g_pm[SPLIT][Bn * Tn];                // partial max
__device__ float g_pl[SPLIT][Bn * Tn];                // partial sum

// ---- f32x2 helpers -------------------------------------------------------
__device__ __forceinline__ unsigned long long pack2(float a, float b) {
    unsigned long long r;
    asm("mov.b64 %0, {%1, %2};" : "=l"(r) : "f"(a), "f"(b));
    return r;
}
__device__ __forceinline__ unsigned long long add2(unsigned long long a, unsigned long long b) {
    unsigned long long r;
    asm("add.rn.f32x2 %0, %1, %2;" : "=l"(r) : "l"(a), "l"(b));
    return r;
}
__device__ __forceinline__ unsigned long long fma2(unsigned long long a, unsigned long long b,
                                                   unsigned long long c) {
    unsigned long long r;
    asm("fma.rn.f32x2 %0, %1, %2, %3;" : "=l"(r) : "l"(a), "l"(b), "l"(c));
    return r;
}
__device__ __forceinline__ void unpack2(float& lo, float& hi, unsigned long long v) {
    asm("mov.b64 {%0, %1}, %2;" : "=f"(lo), "=f"(hi) : "l"(v));
}

// ---------------------------------------------------------------------------
// K1: fused QKV projection. [16384 x 1024] @ [1024 x 192] fp32, smem-tiled.
// ---------------------------------------------------------------------------
__global__ __launch_bounds__(256, 3)
void proj_kernel(const float* __restrict__ x,
                 const float* __restrict__ Wk, const float* __restrict__ bk,
                 const float* __restrict__ Wq, const float* __restrict__ bq,
                 const float* __restrict__ Wv, const float* __restrict__ bv)
{
    __shared__ float xs[32][65];
    __shared__ float ws[64][193];

    const int tid  = threadIdx.x;
    const int tok0 = blockIdx.x * 32;
    const int cl   = tid & 31;
    const int tr   = (tid >> 5) << 2;

    float acc[4][6];
#pragma unroll
    for (int i = 0; i < 4; ++i)
#pragma unroll
        for (int j = 0; j < 6; ++j) acc[i][j] = 0.f;

    for (int k0 = 0; k0 < Dn; k0 += 64) {
        __syncthreads();
        for (int idx = tid; idx < 32 * 64; idx += 256) {
            int k = idx & 63, tk = idx >> 6;
            xs[tk][k] = x[(size_t)(tok0 + tk) * Dn + k0 + k];
        }
        for (int idx = tid; idx < 192 * 64; idx += 256) {
            int k = idx & 63, col = idx >> 6;
            const float* Wsrc = (col < 64) ? Wk : ((col < 128) ? Wq : Wv);
            ws[k][col] = Wsrc[(size_t)(col & 63) * Dn + k0 + k];
        }
        __syncthreads();

#pragma unroll 8
        for (int k = 0; k < 64; ++k) {
            float xv0 = xs[tr + 0][k];
            float xv1 = xs[tr + 1][k];
            float xv2 = xs[tr + 2][k];
            float xv3 = xs[tr + 3][k];
#pragma unroll
            for (int j = 0; j < 6; ++j) {
                float wv = ws[k][cl + 32 * j];
                acc[0][j] = fmaf(xv0, wv, acc[0][j]);
                acc[1][j] = fmaf(xv1, wv, acc[1][j]);
                acc[2][j] = fmaf(xv2, wv, acc[2][j]);
                acc[3][j] = fmaf(xv3, wv, acc[3][j]);
            }
        }
    }

#pragma unroll
    for (int i = 0; i < 4; ++i) {
        int tokg = tok0 + tr + i;
        int b = tokg >> 11;
        int t = tokg & (Tn - 1);
#pragma unroll
        for (int j = 0; j < 6; ++j) {
            int col = cl + 32 * j;
            int h = col & 63;
            if (col < 64) {
                float r = acc[i][j] + bk[h];
                g_k8t[((size_t)b * HSn + h) * Tn + t] = 8.0f * r;
            } else if (col < 128) {
                g_q[(size_t)tokg * HSn + h] = acc[i][j] + bq[h];
            } else {
                g_v[(size_t)tokg * HSn + h] = acc[i][j] + bv[h];
            }
        }
    }
}

// ---------------------------------------------------------------------------
// K2: fused attention, split-KV flash. Block = 8 t-rows x 8 batches x v-half.
// 16 warps: warp w -> batch (w&7), t-half (w>>3) [4 rows per warp].
// rel tile staged XOR-swizzled, read once per (element,batch).
// q staged transposed [b][h][tt] -> LDS.64 broadcast per tt-pair.
// phase A accumulates in f32x2 (2 rows packed).
// ---------------------------------------------------------------------------
#define SREL_WORDS (TQ * HSn * VT)   // 16384
#define SQ_WORDS   (Bn * HSn * TQ)   // 4096
#define SP_WORDS   (Bn * TQ * VT)    // 2048
#define ATTN_SMEM_BYTES ((SREL_WORDS + SQ_WORDS + SP_WORDS) * 4)  // 90112

__global__ __launch_bounds__(512, 2)
void attn_kernel(const float* __restrict__ rel)
{
    extern __shared__ float sm[];
    float* srelT = sm;                 // [tt][h][v] swizzled: v' = v ^ (h&31)
    float* sqT   = sm + SREL_WORDS;    // [b][h][tt]
    float* sp    = sqT + SQ_WORDS;     // [b][tt][v]

    const int tid   = threadIdx.x;
    const int w     = tid >> 5;
    const int lane  = tid & 31;
    const int b     = w & 7;
    const int th4   = (w >> 3) << 2;               // 0 or 4
    const int t0    = blockIdx.x * TQ;
    const int vbase = blockIdx.y * VLEN;

    // stage q transposed: [b][h][tt]
    for (int idx = tid; idx < SQ_WORDS; idx += 512) {
        int h  = idx & 63;
        int tt = (idx >> 6) & 7;
        int bb = idx >> 9;
        sqT[(bb * HSn + h) * TQ + tt] = g_q[((size_t)bb * Tn + t0 + tt) * HSn + h];
    }

    float m[4], l[4], oa0[4], oa1[4];
#pragma unroll
    for (int j = 0; j < 4; ++j) { m[j] = -1e30f; l[j] = 0.f; oa0[j] = 0.f; oa1[j] = 0.f; }

    const float* k8p = g_k8t + (size_t)b * HSn * Tn + vbase;
    const float* vbp = g_v   + (size_t)b * Tn * HSn;
    const float* qb  = sqT + (b * HSn) * TQ + th4;       // + h*TQ
    float*       spw = sp + (b * TQ + th4) * VT;         // warp's 4 rows

    for (int v0 = 0; v0 < VLEN; v0 += VT) {
        __syncthreads();
        // stage rel tile float4-coalesced, swizzled write
        for (int idx = tid; idx < SREL_WORDS / 4; idx += 512) {
            int h4 = idx & 15;            // h = 4*h4
            int v  = (idx >> 4) & 31;
            int tt = idx >> 9;
            const float4 r4 = *(const float4*)
                (rel + ((size_t)(t0 + tt) * Tn + vbase + v0 + v) * HSn + 4 * h4);
            int h = 4 * h4;
            int base = (tt * HSn + h) << 5;
            srelT[ base             + (v ^ ( h      & 31))] = r4.x;
            srelT[(base + 32)       + (v ^ ((h + 1) & 31))] = r4.y;
            srelT[(base + 64)       + (v ^ ((h + 2) & 31))] = r4.z;
            srelT[(base + 96)       + (v ^ ((h + 3) & 31))] = r4.w;
        }
        __syncthreads();

        // ---- Phase A: scores for 4 rows as 2 packed f32x2 accumulators ----
        unsigned long long s2[2];
        s2[0] = 0ull; s2[1] = 0ull;
        const float* kcol = k8p + v0 + lane;

#pragma unroll 4
        for (int h = 0; h < HSn; ++h) {
            float k8 = __ldg(kcol + (size_t)h * Tn);
            unsigned long long k8d = pack2(k8, k8);
            const float* qh = qb + h * TQ;
            const float* rp = srelT + ((th4 * HSn + h) << 5) + (lane ^ (h & 31));
#pragma unroll
            for (int j = 0; j < 2; ++j) {
                unsigned long long q2 =
                    *(const unsigned long long*)(qh + 2 * j);      // LDS.64 bcast
                float rv0 = rp[(2 * j)     * (HSn * VT)];
                float rv1 = rp[(2 * j + 1) * (HSn * VT)];
                unsigned long long t2 = add2(k8d, pack2(rv0, rv1));
                s2[j] = fma2(q2, t2, s2[j]);
            }
        }

        // ---- Phase B: online softmax per row (warp owns full row) ----
        float s[4];
        unpack2(s[0], s[1], s2[0]);
        unpack2(s[2], s[3], s2[1]);
#pragma unroll
        for (int j = 0; j < 4; ++j) {
            float mt = s[j];
#pragma unroll
            for (int o = 16; o > 0; o >>= 1)
                mt = fmaxf(mt, __shfl_xor_sync(0xffffffffu, mt, o));
            float mn = fmaxf(m[j], mt);
            float sc = __expf(m[j] - mn);
            float p  = __expf(s[j] - mn);
            m[j] = mn;
            l[j] = l[j] * sc + p;
            oa0[j] *= sc; oa1[j] *= sc;
            spw[j * VT + lane] = p;
        }
        __syncwarp();

        // ---- Phase C: PV, lanes over h; p via float4 broadcast ----
#pragma unroll
        for (int vq = 0; vq < VT; vq += 4) {
            float4 p0 = *(const float4*)(spw + 0 * VT + vq);
            float4 p1 = *(const float4*)(spw + 1 * VT + vq);
            float4 p2 = *(const float4*)(spw + 2 * VT + vq);
            float4 p3 = *(const float4*)(spw + 3 * VT + vq);
            const float* pa0 = (const float*)&p0;
            const float* pa1 = (const float*)&p1;
            const float* pa2 = (const float*)&p2;
            const float* pa3 = (const float*)&p3;
#pragma unroll
            for (int i = 0; i < 4; ++i) {
                const float* vr = vbp + (size_t)(vbase + v0 + vq + i) * HSn;
                float ve0 = vr[lane];
                float ve1 = vr[lane + 32];
                oa0[0] = fmaf(pa0[i], ve0, oa0[0]); oa1[0] = fmaf(pa0[i], ve1, oa1[0]);
                oa0[1] = fmaf(pa1[i], ve0, oa0[1]); oa1[1] = fmaf(pa1[i], ve1, oa1[1]);
                oa0[2] = fmaf(pa2[i], ve0, oa0[2]); oa1[2] = fmaf(pa2[i], ve1, oa1[2]);
                oa0[3] = fmaf(pa3[i], ve0, oa0[3]); oa1[3] = fmaf(pa3[i], ve1, oa1[3]);
            }
        }
        __syncwarp();
    }

    // ---- write unnormalized partials ----
    const int sidx = blockIdx.y;
#pragma unroll
    for (int j = 0; j < 4; ++j) {
        float lt = l[j];
#pragma unroll
        for (int o = 16; o > 0; o >>= 1)
            lt += __shfl_xor_sync(0xffffffffu, lt, o);
        int row = b * Tn + t0 + th4 + j;
        size_t o0 = (size_t)row * HSn;
        g_po[sidx][o0 + lane]      = oa0[j];
        g_po[sidx][o0 + lane + 32] = oa1[j];
        if (lane == 0) { g_pm[sidx][row] = m[j]; g_pl[sidx][row] = lt; }
    }
}

// ---------------------------------------------------------------------------
// K3: merge the SPLIT partials -> normalized output
// ---------------------------------------------------------------------------
__global__ __launch_bounds__(256)
void merge_kernel(float* __restrict__ out)
{
    int idx = blockIdx.x * 256 + threadIdx.x;   // over B*T*HS
    int row = idx >> 6;
    float m0 = g_pm[0][row], m1 = g_pm[1][row];
    float M  = fmaxf(m0, m1);
    float a0 = __expf(m0 - M), a1 = __expf(m1 - M);
    float denom = a0 * g_pl[0][row] + a1 * g_pl[1][row];
    out[idx] = (a0 * g_po[0][idx] + a1 * g_po[1][idx]) / denom;
}

// ---------------------------------------------------------------------------
extern "C" void kernel_launch(void* const* d_in, const int* in_sizes, int n_in,
                              void* d_out, int out_size)
{
    const float* x   = (const float*)d_in[0];
    const float* Wk  = (const float*)d_in[1];
    const float* bk  = (const float*)d_in[2];
    const float* Wq  = (const float*)d_in[3];
    const float* bq  = (const float*)d_in[4];
    const float* Wv  = (const float*)d_in[5];
    const float* bv  = (const float*)d_in[6];
    const float* rel = (const float*)d_in[7];
    float* out = (float*)d_out;

    cudaFuncSetAttribute(attn_kernel,
                         cudaFuncAttributeMaxDynamicSharedMemorySize,
                         ATTN_SMEM_BYTES);

    proj_kernel<<<(Bn * Tn) / 32, 256>>>(x, Wk, bk, Wq, bq, Wv, bv);
    attn_kernel<<<dim3(Tn / TQ, SPLIT), 512, ATTN_SMEM_BYTES>>>(rel);
    merge_kernel<<<(Bn * Tn * HSn) / 256, 256>>>(out);
}

// round 3
// speedup vs baseline: 1.0548x; 1.0011x over previous
#include <cuda_runtime.h>
#include <cstdint>
#include <cstddef>

#define Bn 8
#define Tn 2048
#define Dn 1024
#define HSn 64
#define TQ 8
#define VT 32
#define SPLIT 2
#define VLEN (Tn / SPLIT)

// Scratch (allocation-free rule: __device__ globals)
__device__ float g_q[(size_t)Bn * Tn * HSn];      // [b][t][h]
__device__ float g_k8t[(size_t)Bn * HSn * Tn];    // [b][h][t], pre-scaled by 8
__device__ float g_v[(size_t)Bn * Tn * HSn];      // [b][t][h]
__device__ float g_po[SPLIT][(size_t)Bn * Tn * HSn];  // unnormalized partial O
__device__ float g_pm[SPLIT][Bn * Tn];                // partial max
__device__ float g_pl[SPLIT][Bn * Tn];                // partial sum

// ---- f32x2 helpers -------------------------------------------------------
__device__ __forceinline__ unsigned long long pack2(float a, float b) {
    unsigned long long r;
    asm("mov.b64 %0, {%1, %2};" : "=l"(r) : "f"(a), "f"(b));
    return r;
}
__device__ __forceinline__ unsigned long long add2(unsigned long long a, unsigned long long b) {
    unsigned long long r;
    asm("add.rn.f32x2 %0, %1, %2;" : "=l"(r) : "l"(a), "l"(b));
    return r;
}
__device__ __forceinline__ unsigned long long fma2(unsigned long long a, unsigned long long b,
                                                   unsigned long long c) {
    unsigned long long r;
    asm("fma.rn.f32x2 %0, %1, %2, %3;" : "=l"(r) : "l"(a), "l"(b), "l"(c));
    return r;
}
__device__ __forceinline__ void unpack2(float& lo, float& hi, unsigned long long v) {
    asm("mov.b64 {%0, %1}, %2;" : "=f"(lo), "=f"(hi) : "l"(v));
}

// ---------------------------------------------------------------------------
// K1: fused QKV projection. [16384 x 1024] @ [1024 x 192] fp32, smem-tiled.
// ---------------------------------------------------------------------------
__global__ __launch_bounds__(256, 3)
void proj_kernel(const float* __restrict__ x,
                 const float* __restrict__ Wk, const float* __restrict__ bk,
                 const float* __restrict__ Wq, const float* __restrict__ bq,
                 const float* __restrict__ Wv, const float* __restrict__ bv)
{
    __shared__ float xs[32][65];
    __shared__ float ws[64][193];

    const int tid  = threadIdx.x;
    const int tok0 = blockIdx.x * 32;
    const int cl   = tid & 31;
    const int tr   = (tid >> 5) << 2;

    float acc[4][6];
#pragma unroll
    for (int i = 0; i < 4; ++i)
#pragma unroll
        for (int j = 0; j < 6; ++j) acc[i][j] = 0.f;

    for (int k0 = 0; k0 < Dn; k0 += 64) {
        __syncthreads();
        for (int idx = tid; idx < 32 * 64; idx += 256) {
            int k = idx & 63, tk = idx >> 6;
            xs[tk][k] = x[(size_t)(tok0 + tk) * Dn + k0 + k];
        }
        for (int idx = tid; idx < 192 * 64; idx += 256) {
            int k = idx & 63, col = idx >> 6;
            const float* Wsrc = (col < 64) ? Wk : ((col < 128) ? Wq : Wv);
            ws[k][col] = Wsrc[(size_t)(col & 63) * Dn + k0 + k];
        }
        __syncthreads();

#pragma unroll 8
        for (int k = 0; k < 64; ++k) {
            float xv0 = xs[tr + 0][k];
            float xv1 = xs[tr + 1][k];
            float xv2 = xs[tr + 2][k];
            float xv3 = xs[tr + 3][k];
#pragma unroll
            for (int j = 0; j < 6; ++j) {
                float wv = ws[k][cl + 32 * j];
                acc[0][j] = fmaf(xv0, wv, acc[0][j]);
                acc[1][j] = fmaf(xv1, wv, acc[1][j]);
                acc[2][j] = fmaf(xv2, wv, acc[2][j]);
                acc[3][j] = fmaf(xv3, wv, acc[3][j]);
            }
        }
    }

#pragma unroll
    for (int i = 0; i < 4; ++i) {
        int tokg = tok0 + tr + i;
        int b = tokg >> 11;
        int t = tokg & (Tn - 1);
#pragma unroll
        for (int j = 0; j < 6; ++j) {
            int col = cl + 32 * j;
            int h = col & 63;
            if (col < 64) {
                float r = acc[i][j] + bk[h];
                g_k8t[((size_t)b * HSn + h) * Tn + t] = 8.0f * r;
            } else if (col < 128) {
                g_q[(size_t)tokg * HSn + h] = acc[i][j] + bq[h];
            } else {
                g_v[(size_t)tokg * HSn + h] = acc[i][j] + bv[h];
            }
        }
    }
}

// ---------------------------------------------------------------------------
// K2: fused attention, split-KV flash. Block = 8 t-rows x 8 batches x v-half.
// 16 warps: warp w -> batch (w&7), t-half (w>>3) [4 rows per warp].
// rel tile staged XOR-swizzled, read once per (element,batch).
// q staged transposed [b][h][tt] -> LDS.64 broadcast per tt-pair.
// phase A accumulates in f32x2 (2 rows packed).
// ---------------------------------------------------------------------------
#define SREL_WORDS (TQ * HSn * VT)   // 16384
#define SQ_WORDS   (Bn * HSn * TQ)   // 4096
#define SP_WORDS   (Bn * TQ * VT)    // 2048
#define ATTN_SMEM_BYTES ((SREL_WORDS + SQ_WORDS + SP_WORDS) * 4)  // 90112

__global__ __launch_bounds__(512, 2)
void attn_kernel(const float* __restrict__ rel)
{
    extern __shared__ float sm[];
    float* srelT = sm;                 // [tt][h][v] swizzled: v' = v ^ (h&31)
    float* sqT   = sm + SREL_WORDS;    // [b][h][tt]
    float* sp    = sqT + SQ_WORDS;     // [b][tt][v]

    const int tid   = threadIdx.x;
    const int w     = tid >> 5;
    const int lane  = tid & 31;
    const int b     = w & 7;
    const int th4   = (w >> 3) << 2;               // 0 or 4
    const int t0    = blockIdx.x * TQ;
    const int vbase = blockIdx.y * VLEN;

    // stage q transposed: [b][h][tt]
    for (int idx = tid; idx < SQ_WORDS; idx += 512) {
        int h  = idx & 63;
        int tt = (idx >> 6) & 7;
        int bb = idx >> 9;
        sqT[(bb * HSn + h) * TQ + tt] = g_q[((size_t)bb * Tn + t0 + tt) * HSn + h];
    }

    float m[4], l[4], oa0[4], oa1[4];
#pragma unroll
    for (int j = 0; j < 4; ++j) { m[j] = -1e30f; l[j] = 0.f; oa0[j] = 0.f; oa1[j] = 0.f; }

    const float* k8p = g_k8t + (size_t)b * HSn * Tn + vbase;
    const float* vbp = g_v   + (size_t)b * Tn * HSn;
    const float* qb  = sqT + (b * HSn) * TQ + th4;       // + h*TQ
    float*       spw = sp + (b * TQ + th4) * VT;         // warp's 4 rows

    for (int v0 = 0; v0 < VLEN; v0 += VT) {
        __syncthreads();
        // stage rel tile float4-coalesced, swizzled write
        for (int idx = tid; idx < SREL_WORDS / 4; idx += 512) {
            int h4 = idx & 15;            // h = 4*h4
            int v  = (idx >> 4) & 31;
            int tt = idx >> 9;
            const float4 r4 = *(const float4*)
                (rel + ((size_t)(t0 + tt) * Tn + vbase + v0 + v) * HSn + 4 * h4);
            int h = 4 * h4;
            int base = (tt * HSn + h) << 5;
            srelT[ base             + (v ^ ( h      & 31))] = r4.x;
            srelT[(base + 32)       + (v ^ ((h + 1) & 31))] = r4.y;
            srelT[(base + 64)       + (v ^ ((h + 2) & 31))] = r4.z;
            srelT[(base + 96)       + (v ^ ((h + 3) & 31))] = r4.w;
        }
        __syncthreads();

        // ---- Phase A: scores for 4 rows as 2 packed f32x2 accumulators ----
        unsigned long long s2[2];
        s2[0] = 0ull; s2[1] = 0ull;
        const float* kcol = k8p + v0 + lane;

#pragma unroll 4
        for (int h = 0; h < HSn; ++h) {
            float k8 = __ldg(kcol + (size_t)h * Tn);
            unsigned long long k8d = pack2(k8, k8);
            const float* qh = qb + h * TQ;
            const float* rp = srelT + ((th4 * HSn + h) << 5) + (lane ^ (h & 31));
#pragma unroll
            for (int j = 0; j < 2; ++j) {
                unsigned long long q2 =
                    *(const unsigned long long*)(qh + 2 * j);      // LDS.64 bcast
                float rv0 = rp[(2 * j)     * (HSn * VT)];
                float rv1 = rp[(2 * j + 1) * (HSn * VT)];
                unsigned long long t2 = add2(k8d, pack2(rv0, rv1));
                s2[j] = fma2(q2, t2, s2[j]);
            }
        }

        // ---- Phase B: online softmax per row (warp owns full row) ----
        float s[4];
        unpack2(s[0], s[1], s2[0]);
        unpack2(s[2], s[3], s2[1]);
#pragma unroll
        for (int j = 0; j < 4; ++j) {
            float mt = s[j];
#pragma unroll
            for (int o = 16; o > 0; o >>= 1)
                mt = fmaxf(mt, __shfl_xor_sync(0xffffffffu, mt, o));
            float mn = fmaxf(m[j], mt);
            float sc = __expf(m[j] - mn);
            float p  = __expf(s[j] - mn);
            m[j] = mn;
            l[j] = l[j] * sc + p;
            oa0[j] *= sc; oa1[j] *= sc;
            spw[j * VT + lane] = p;
        }
        __syncwarp();

        // ---- Phase C: PV, lanes over h; p via float4 broadcast ----
#pragma unroll
        for (int vq = 0; vq < VT; vq += 4) {
            float4 p0 = *(const float4*)(spw + 0 * VT + vq);
            float4 p1 = *(const float4*)(spw + 1 * VT + vq);
            float4 p2 = *(const float4*)(spw + 2 * VT + vq);
            float4 p3 = *(const float4*)(spw + 3 * VT + vq);
            const float* pa0 = (const float*)&p0;
            const float* pa1 = (const float*)&p1;
            const float* pa2 = (const float*)&p2;
            const float* pa3 = (const float*)&p3;
#pragma unroll
            for (int i = 0; i < 4; ++i) {
                const float* vr = vbp + (size_t)(vbase + v0 + vq + i) * HSn;
                float ve0 = vr[lane];
                float ve1 = vr[lane + 32];
                oa0[0] = fmaf(pa0[i], ve0, oa0[0]); oa1[0] = fmaf(pa0[i], ve1, oa1[0]);
                oa0[1] = fmaf(pa1[i], ve0, oa0[1]); oa1[1] = fmaf(pa1[i], ve1, oa1[1]);
                oa0[2] = fmaf(pa2[i], ve0, oa0[2]); oa1[2] = fmaf(pa2[i], ve1, oa1[2]);
                oa0[3] = fmaf(pa3[i], ve0, oa0[3]); oa1[3] = fmaf(pa3[i], ve1, oa1[3]);
            }
        }
        __syncwarp();
    }

    // ---- write unnormalized partials ----
    const int sidx = blockIdx.y;
#pragma unroll
    for (int j = 0; j < 4; ++j) {
        float lt = l[j];
#pragma unroll
        for (int o = 16; o > 0; o >>= 1)
            lt += __shfl_xor_sync(0xffffffffu, lt, o);
        int row = b * Tn + t0 + th4 + j;
        size_t o0 = (size_t)row * HSn;
        g_po[sidx][o0 + lane]      = oa0[j];
        g_po[sidx][o0 + lane + 32] = oa1[j];
        if (lane == 0) { g_pm[sidx][row] = m[j]; g_pl[sidx][row] = lt; }
    }
}

// ---------------------------------------------------------------------------
// K3: merge the SPLIT partials -> normalized output
// ---------------------------------------------------------------------------
__global__ __launch_bounds__(256)
void merge_kernel(float* __restrict__ out)
{
    int idx = blockIdx.x * 256 + threadIdx.x;   // over B*T*HS
    int row = idx >> 6;
    float m0 = g_pm[0][row], m1 = g_pm[1][row];
    float M  = fmaxf(m0, m1);
    float a0 = __expf(m0 - M), a1 = __expf(m1 - M);
    float denom = a0 * g_pl[0][row] + a1 * g_pl[1][row];
    out[idx] = (a0 * g_po[0][idx] + a1 * g_po[1][idx]) / denom;
}

// ---------------------------------------------------------------------------
extern "C" void kernel_launch(void* const* d_in, const int* in_sizes, int n_in,
                              void* d_out, int out_size)
{
    const float* x   = (const float*)d_in[0];
    const float* Wk  = (const float*)d_in[1];
    const float* bk  = (const float*)d_in[2];
    const float* Wq  = (const float*)d_in[3];
    const float* bq  = (const float*)d_in[4];
    const float* Wv  = (const float*)d_in[5];
    const float* bv  = (const float*)d_in[6];
    const float* rel = (const float*)d_in[7];
    float* out = (float*)d_out;

    cudaFuncSetAttribute(attn_kernel,
                         cudaFuncAttributeMaxDynamicSharedMemorySize,
                         ATTN_SMEM_BYTES);

    proj_kernel<<<(Bn * Tn) / 32, 256>>>(x, Wk, bk, Wq, bq, Wv, bv);
    attn_kernel<<<dim3(Tn / TQ, SPLIT), 512, ATTN_SMEM_BYTES>>>(rel);
    merge_kernel<<<(Bn * Tn * HSn) / 256, 256>>>(out);
}

// round 4
// speedup vs baseline: 1.0555x; 1.0006x over previous
#include <cuda_runtime.h>
#include <cstdint>
#include <cstddef>

#define Bn 8
#define Tn 2048
#define Dn 1024
#define HSn 64
#define TQ 8
#define VT 32
#define SPLIT 2
#define VLEN (Tn / SPLIT)

// Scratch (allocation-free rule: __device__ globals)
__device__ float g_q[(size_t)Bn * Tn * HSn];      // [b][t][h]
__device__ float g_k8t[(size_t)Bn * HSn * Tn];    // [b][h][t], pre-scaled by 8
__device__ float g_v[(size_t)Bn * Tn * HSn];      // [b][t][h]
__device__ float g_po[SPLIT][(size_t)Bn * Tn * HSn];  // unnormalized partial O
__device__ float g_pm[SPLIT][Bn * Tn];                // partial max
__device__ float g_pl[SPLIT][Bn * Tn];                // partial sum

// ---- f32x2 helpers -------------------------------------------------------
__device__ __forceinline__ unsigned long long pack2(float a, float b) {
    unsigned long long r;
    asm("mov.b64 %0, {%1, %2};" : "=l"(r) : "f"(a), "f"(b));
    return r;
}
__device__ __forceinline__ unsigned long long add2(unsigned long long a, unsigned long long b) {
    unsigned long long r;
    asm("add.rn.f32x2 %0, %1, %2;" : "=l"(r) : "l"(a), "l"(b));
    return r;
}
__device__ __forceinline__ unsigned long long fma2(unsigned long long a, unsigned long long b,
                                                   unsigned long long c) {
    unsigned long long r;
    asm("fma.rn.f32x2 %0, %1, %2, %3;" : "=l"(r) : "l"(a), "l"(b), "l"(c));
    return r;
}
__device__ __forceinline__ void unpack2(float& lo, float& hi, unsigned long long v) {
    asm("mov.b64 {%0, %1}, %2;" : "=f"(lo), "=f"(hi) : "l"(v));
}

// ---------------------------------------------------------------------------
// K1: fused QKV projection. [16384 x 1024] @ [1024 x 192] fp32, smem-tiled.
// ---------------------------------------------------------------------------
__global__ __launch_bounds__(256, 3)
void proj_kernel(const float* __restrict__ x,
                 const float* __restrict__ Wk, const float* __restrict__ bk,
                 const float* __restrict__ Wq, const float* __restrict__ bq,
                 const float* __restrict__ Wv, const float* __restrict__ bv)
{
    __shared__ float xs[32][65];
    __shared__ float ws[64][193];

    const int tid  = threadIdx.x;
    const int tok0 = blockIdx.x * 32;
    const int cl   = tid & 31;
    const int tr   = (tid >> 5) << 2;

    float acc[4][6];
#pragma unroll
    for (int i = 0; i < 4; ++i)
#pragma unroll
        for (int j = 0; j < 6; ++j) acc[i][j] = 0.f;

    for (int k0 = 0; k0 < Dn; k0 += 64) {
        __syncthreads();
        for (int idx = tid; idx < 32 * 64; idx += 256) {
            int k = idx & 63, tk = idx >> 6;
            xs[tk][k] = x[(size_t)(tok0 + tk) * Dn + k0 + k];
        }
        for (int idx = tid; idx < 192 * 64; idx += 256) {
            int k = idx & 63, col = idx >> 6;
            const float* Wsrc = (col < 64) ? Wk : ((col < 128) ? Wq : Wv);
            ws[k][col] = Wsrc[(size_t)(col & 63) * Dn + k0 + k];
        }
        __syncthreads();

#pragma unroll 8
        for (int k = 0; k < 64; ++k) {
            float xv0 = xs[tr + 0][k];
            float xv1 = xs[tr + 1][k];
            float xv2 = xs[tr + 2][k];
            float xv3 = xs[tr + 3][k];
#pragma unroll
            for (int j = 0; j < 6; ++j) {
                float wv = ws[k][cl + 32 * j];
                acc[0][j] = fmaf(xv0, wv, acc[0][j]);
                acc[1][j] = fmaf(xv1, wv, acc[1][j]);
                acc[2][j] = fmaf(xv2, wv, acc[2][j]);
                acc[3][j] = fmaf(xv3, wv, acc[3][j]);
            }
        }
    }

#pragma unroll
    for (int i = 0; i < 4; ++i) {
        int tokg = tok0 + tr + i;
        int b = tokg >> 11;
        int t = tokg & (Tn - 1);
#pragma unroll
        for (int j = 0; j < 6; ++j) {
            int col = cl + 32 * j;
            int h = col & 63;
            if (col < 64) {
                float r = acc[i][j] + bk[h];
                g_k8t[((size_t)b * HSn + h) * Tn + t] = 8.0f * r;
            } else if (col < 128) {
                g_q[(size_t)tokg * HSn + h] = acc[i][j] + bq[h];
            } else {
                g_v[(size_t)tokg * HSn + h] = acc[i][j] + bv[h];
            }
        }
    }
}

// ---------------------------------------------------------------------------
// K2: fused attention, split-KV flash. Block = 8 t-rows x 8 batches x v-half.
// 16 warps: warp w -> batch (w&7), t-half (w>>3) [4 rows per warp].
// rel tile staged XOR-swizzled, read once per (element,batch).
// q staged transposed [b][h][tt] -> LDS.64 broadcast per tt-pair.
// phase A accumulates in f32x2 (2 rows packed).
// ---------------------------------------------------------------------------
#define SREL_WORDS (TQ * HSn * VT)   // 16384
#define SQ_WORDS   (Bn * HSn * TQ)   // 4096
#define SP_WORDS   (Bn * TQ * VT)    // 2048
#define ATTN_SMEM_BYTES ((SREL_WORDS + SQ_WORDS + SP_WORDS) * 4)  // 90112

__global__ __launch_bounds__(512, 2)
void attn_kernel(const float* __restrict__ rel)
{
    extern __shared__ float sm[];
    float* srelT = sm;                 // [tt][h][v] swizzled: v' = v ^ (h&31)
    float* sqT   = sm + SREL_WORDS;    // [b][h][tt]
    float* sp    = sqT + SQ_WORDS;     // [b][tt][v]

    const int tid   = threadIdx.x;
    const int w     = tid >> 5;
    const int lane  = tid & 31;
    const int b     = w & 7;
    const int th4   = (w >> 3) << 2;               // 0 or 4
    const int t0    = blockIdx.x * TQ;
    const int vbase = blockIdx.y * VLEN;

    // stage q transposed: [b][h][tt]
    for (int idx = tid; idx < SQ_WORDS; idx += 512) {
        int h  = idx & 63;
        int tt = (idx >> 6) & 7;
        int bb = idx >> 9;
        sqT[(bb * HSn + h) * TQ + tt] = g_q[((size_t)bb * Tn + t0 + tt) * HSn + h];
    }

    float m[4], l[4], oa0[4], oa1[4];
#pragma unroll
    for (int j = 0; j < 4; ++j) { m[j] = -1e30f; l[j] = 0.f; oa0[j] = 0.f; oa1[j] = 0.f; }

    const float* k8p = g_k8t + (size_t)b * HSn * Tn + vbase;
    const float* vbp = g_v   + (size_t)b * Tn * HSn;
    const float* qb  = sqT + (b * HSn) * TQ + th4;       // + h*TQ
    float*       spw = sp + (b * TQ + th4) * VT;         // warp's 4 rows

    for (int v0 = 0; v0 < VLEN; v0 += VT) {
        __syncthreads();
        // stage rel tile float4-coalesced, swizzled write
        for (int idx = tid; idx < SREL_WORDS / 4; idx += 512) {
            int h4 = idx & 15;            // h = 4*h4
            int v  = (idx >> 4) & 31;
            int tt = idx >> 9;
            const float4 r4 = *(const float4*)
                (rel + ((size_t)(t0 + tt) * Tn + vbase + v0 + v) * HSn + 4 * h4);
            int h = 4 * h4;
            int base = (tt * HSn + h) << 5;
            srelT[ base             + (v ^ ( h      & 31))] = r4.x;
            srelT[(base + 32)       + (v ^ ((h + 1) & 31))] = r4.y;
            srelT[(base + 64)       + (v ^ ((h + 2) & 31))] = r4.z;
            srelT[(base + 96)       + (v ^ ((h + 3) & 31))] = r4.w;
        }
        __syncthreads();

        // ---- Phase A: scores for 4 rows as 2 packed f32x2 accumulators ----
        unsigned long long s2[2];
        s2[0] = 0ull; s2[1] = 0ull;
        const float* kcol = k8p + v0 + lane;

#pragma unroll 4
        for (int h = 0; h < HSn; ++h) {
            float k8 = __ldg(kcol + (size_t)h * Tn);
            unsigned long long k8d = pack2(k8, k8);
            const float* qh = qb + h * TQ;
            const float* rp = srelT + ((th4 * HSn + h) << 5) + (lane ^ (h & 31));
#pragma unroll
            for (int j = 0; j < 2; ++j) {
                unsigned long long q2 =
                    *(const unsigned long long*)(qh + 2 * j);      // LDS.64 bcast
                float rv0 = rp[(2 * j)     * (HSn * VT)];
                float rv1 = rp[(2 * j + 1) * (HSn * VT)];
                unsigned long long t2 = add2(k8d, pack2(rv0, rv1));
                s2[j] = fma2(q2, t2, s2[j]);
            }
        }

        // ---- Phase B: online softmax per row (warp owns full row) ----
        float s[4];
        unpack2(s[0], s[1], s2[0]);
        unpack2(s[2], s[3], s2[1]);
#pragma unroll
        for (int j = 0; j < 4; ++j) {
            float mt = s[j];
#pragma unroll
            for (int o = 16; o > 0; o >>= 1)
                mt = fmaxf(mt, __shfl_xor_sync(0xffffffffu, mt, o));
            float mn = fmaxf(m[j], mt);
            float sc = __expf(m[j] - mn);
            float p  = __expf(s[j] - mn);
            m[j] = mn;
            l[j] = l[j] * sc + p;
            oa0[j] *= sc; oa1[j] *= sc;
            spw[j * VT + lane] = p;
        }
        __syncwarp();

        // ---- Phase C: PV, lanes over h; p via float4 broadcast ----
#pragma unroll
        for (int vq = 0; vq < VT; vq += 4) {
            float4 p0 = *(const float4*)(spw + 0 * VT + vq);
            float4 p1 = *(const float4*)(spw + 1 * VT + vq);
            float4 p2 = *(const float4*)(spw + 2 * VT + vq);
            float4 p3 = *(const float4*)(spw + 3 * VT + vq);
            const float* pa0 = (const float*)&p0;
            const float* pa1 = (const float*)&p1;
            const float* pa2 = (const float*)&p2;
            const float* pa3 = (const float*)&p3;
#pragma unroll
            for (int i = 0; i < 4; ++i) {
                const float* vr = vbp + (size_t)(vbase + v0 + vq + i) * HSn;
                float ve0 = vr[lane];
                float ve1 = vr[lane + 32];
                oa0[0] = fmaf(pa0[i], ve0, oa0[0]); oa1[0] = fmaf(pa0[i], ve1, oa1[0]);
                oa0[1] = fmaf(pa1[i], ve0, oa0[1]); oa1[1] = fmaf(pa1[i], ve1, oa1[1]);
                oa0[2] = fmaf(pa2[i], ve0, oa0[2]); oa1[2] = fmaf(pa2[i], ve1, oa1[2]);
                oa0[3] = fmaf(pa3[i], ve0, oa0[3]); oa1[3] = fmaf(pa3[i], ve1, oa1[3]);
            }
        }
        __syncwarp();
    }

    // ---- write unnormalized partials ----
    const int sidx = blockIdx.y;
#pragma unroll
    for (int j = 0; j < 4; ++j) {
        float lt = l[j];
#pragma unroll
        for (int o = 16; o > 0; o >>= 1)
            lt += __shfl_xor_sync(0xffffffffu, lt, o);
        int row = b * Tn + t0 + th4 + j;
        size_t o0 = (size_t)row * HSn;
        g_po[sidx][o0 + lane]      = oa0[j];
        g_po[sidx][o0 + lane + 32] = oa1[j];
        if (lane == 0) { g_pm[sidx][row] = m[j]; g_pl[sidx][row] = lt; }
    }
}

// ---------------------------------------------------------------------------
// K3: merge the SPLIT partials -> normalized output
// ---------------------------------------------------------------------------
__global__ __launch_bounds__(256)
void merge_kernel(float* __restrict__ out)
{
    int idx = blockIdx.x * 256 + threadIdx.x;   // over B*T*HS
    int row = idx >> 6;
    float m0 = g_pm[0][row], m1 = g_pm[1][row];
    float M  = fmaxf(m0, m1);
    float a0 = __expf(m0 - M), a1 = __expf(m1 - M);
    float denom = a0 * g_pl[0][row] + a1 * g_pl[1][row];
    out[idx] = (a0 * g_po[0][idx] + a1 * g_po[1][idx]) / denom;
}

// ---------------------------------------------------------------------------
extern "C" void kernel_launch(void* const* d_in, const int* in_sizes, int n_in,
                              void* d_out, int out_size)
{
    const float* x   = (const float*)d_in[0];
    const float* Wk  = (const float*)d_in[1];
    const float* bk  = (const float*)d_in[2];
    const float* Wq  = (const float*)d_in[3];
    const float* bq  = (const float*)d_in[4];
    const float* Wv  = (const float*)d_in[5];
    const float* bv  = (const float*)d_in[6];
    const float* rel = (const float*)d_in[7];
    float* out = (float*)d_out;

    cudaFuncSetAttribute(attn_kernel,
                         cudaFuncAttributeMaxDynamicSharedMemorySize,
                         ATTN_SMEM_BYTES);

    proj_kernel<<<(Bn * Tn) / 32, 256>>>(x, Wk, bk, Wq, bq, Wv, bv);
    attn_kernel<<<dim3(Tn / TQ, SPLIT), 512, ATTN_SMEM_BYTES>>>(rel);
    merge_kernel<<<(Bn * Tn * HSn) / 256, 256>>>(out);
}

// round 5
// speedup vs baseline: 1.2464x; 1.1809x over previous
#include <cuda_runtime.h>
#include <cstdint>
#include <cstddef>

typedef unsigned long long ull;

#define Bn 8
#define Tn 2048
#define Dn 1024
#define HSn 64
#define TQ 8
#define VT 32
#define SPLIT 4
#define VLEN (Tn / SPLIT)          // 512
#define NTILE (VLEN / VT)          // 16
#define NSTG (NTILE * 2)           // 32 stages (tile x h-half)

// Scratch (allocation-free rule: __device__ globals)
__device__ float g_q [(size_t)Bn * Tn * HSn];            // [b][t][h]
__device__ float g_k4[(size_t)Bn * 16 * Tn * 4];         // [b][hg(16)][t][4], pre-scaled by 8
__device__ float g_v [(size_t)Bn * Tn * HSn];            // [b][t][h]
__device__ float g_po[SPLIT][(size_t)Bn * Tn * HSn];
__device__ float g_pm[SPLIT][Bn * Tn];
__device__ float g_pl[SPLIT][Bn * Tn];

// ---- f32x2 + wide-load helpers --------------------------------------------
__device__ __forceinline__ ull pack2(float a, float b) {
    ull r; asm("mov.b64 %0, {%1, %2};" : "=l"(r) : "f"(a), "f"(b)); return r;
}
__device__ __forceinline__ ull add2(ull a, ull b) {
    ull r; asm("add.rn.f32x2 %0, %1, %2;" : "=l"(r) : "l"(a), "l"(b)); return r;
}
__device__ __forceinline__ ull fma2(ull a, ull b, ull c) {
    ull r; asm("fma.rn.f32x2 %0, %1, %2, %3;" : "=l"(r) : "l"(a), "l"(b), "l"(c)); return r;
}
__device__ __forceinline__ void unpack2(float& lo, float& hi, ull v) {
    asm("mov.b64 {%0, %1}, %2;" : "=f"(lo), "=f"(hi) : "l"(v));
}
__device__ __forceinline__ void lds_v2(ull& a, ull& b, uint32_t addr) {
    asm volatile("ld.shared.v2.b64 {%0, %1}, [%2];" : "=l"(a), "=l"(b) : "r"(addr));
}
__device__ __forceinline__ void ldg_v2(ull& a, ull& b, const void* p) {
    asm volatile("ld.global.nc.v2.b64 {%0, %1}, [%2];" : "=l"(a), "=l"(b) : "l"(p));
}
__device__ __forceinline__ void cp_async16(uint32_t dst, const void* src) {
    asm volatile("cp.async.cg.shared.global [%0], [%1], 16;" :: "r"(dst), "l"(src) : "memory");
}

// ---------------------------------------------------------------------------
// K1: fused QKV projection, f32x2 over token pairs.
// Block: 32 tokens x 192 cols, 256 threads; warp lane = col, 4 tokens/thread.
// ---------------------------------------------------------------------------
__global__ __launch_bounds__(256, 3)
void proj_kernel(const float* __restrict__ x,
                 const float* __restrict__ Wk, const float* __restrict__ bk,
                 const float* __restrict__ Wq, const float* __restrict__ bq,
                 const float* __restrict__ Wv, const float* __restrict__ bv)
{
    __shared__ float xsT[64 * 36];     // [k][tok], row 36 floats (16B-aligned reads)
    __shared__ float ws[64][193];      // [k][col]

    const int tid  = threadIdx.x;
    const int tok0 = blockIdx.x * 32;
    const int cl   = tid & 31;
    const int tr   = (tid >> 5) << 2;   // token base for this warp (uniform in warp)

    const uint32_t xsT_u = (uint32_t)__cvta_generic_to_shared(xsT);

    ull acc2[2][6];
#pragma unroll
    for (int i = 0; i < 2; ++i)
#pragma unroll
        for (int j = 0; j < 6; ++j) acc2[i][j] = 0ull;

    for (int k0 = 0; k0 < Dn; k0 += 64) {
        __syncthreads();
        for (int idx = tid; idx < 32 * 64; idx += 256) {
            int k = idx & 63, tk = idx >> 6;
            xsT[k * 36 + tk] = x[(size_t)(tok0 + tk) * Dn + k0 + k];
        }
        for (int idx = tid; idx < 192 * 64; idx += 256) {
            int k = idx & 63, col = idx >> 6;
            const float* Wsrc = (col < 64) ? Wk : ((col < 128) ? Wq : Wv);
            ws[k][col] = Wsrc[(size_t)(col & 63) * Dn + k0 + k];
        }
        __syncthreads();

#pragma unroll 8
        for (int k = 0; k < 64; ++k) {
            ull x2a, x2b;   // (tok tr,tr+1), (tok tr+2,tr+3) — broadcast LDS
            lds_v2(x2a, x2b, xsT_u + (uint32_t)(k * 36 + tr) * 4u);
#pragma unroll
            for (int j = 0; j < 6; ++j) {
                float wv = ws[k][cl + 32 * j];
                ull wd = pack2(wv, wv);
                acc2[0][j] = fma2(x2a, wd, acc2[0][j]);
                acc2[1][j] = fma2(x2b, wd, acc2[1][j]);
            }
        }
    }

#pragma unroll
    for (int j = 0; j < 6; ++j) {
        float a[4];
        unpack2(a[0], a[1], acc2[0][j]);
        unpack2(a[2], a[3], acc2[1][j]);
        int col = cl + 32 * j;
        int h = col & 63;
#pragma unroll
        for (int i = 0; i < 4; ++i) {
            int tokg = tok0 + tr + i;
            int b = tokg >> 11;
            int t = tokg & (Tn - 1);
            if (col < 64) {
                float r = a[i] + bk[h];
                g_k4[(((size_t)(b * 16 + (h >> 2)) * Tn + t) << 2) + (h & 3)] = 8.0f * r;
            } else if (col < 128) {
                g_q[(size_t)tokg * HSn + h] = a[i] + bq[h];
            } else {
                g_v[(size_t)tokg * HSn + h] = a[i] + bv[h];
            }
        }
    }
}

// ---------------------------------------------------------------------------
// K2: fused attention, split-KV, cp.async double-buffered rel pipeline.
// Block: 8 t-rows x 8 batches x (1/SPLIT of keys). 16 warps: warp w -> batch
// (w&7), t-half (w>>3). Stage = (tile, h-half): 32KB natural-layout rel
// buffer [tt][hh][v] float4, swizzle v^hh.
// ---------------------------------------------------------------------------
#define SBUF_BYTES 32768
#define SQ_OFF  (2 * SBUF_BYTES)                    // 65536
#define SP_OFF  (SQ_OFF + Bn * TQ * HSn * 4)        // +16384
#define ATTN_SMEM_BYTES (SP_OFF + 16 * 4 * 32 * 4)  // +8192 = 90112

__global__ __launch_bounds__(512, 1)
void attn_kernel(const float* __restrict__ rel)
{
    extern __shared__ float smf[];
    const uint32_t smem0 = (uint32_t)__cvta_generic_to_shared(smf);
    const uint32_t squ   = smem0 + SQ_OFF;

    const int tid  = threadIdx.x;
    const int w    = tid >> 5;
    const int lane = tid & 31;
    const int b    = w & 7;
    const int th4  = (w >> 3) << 2;
    const int t0   = blockIdx.x * TQ;
    const int vbase = blockIdx.y * VLEN;

    // ---- stage q: sq[b][tt][h] (published by first pipeline barrier) ----
    for (int idx = tid; idx < Bn * TQ * HSn; idx += 512) {
        int h  = idx & 63;
        int tt = (idx >> 6) & 7;
        int bb = idx >> 9;
        smf[(SQ_OFF >> 2) + idx] = g_q[((size_t)bb * Tn + t0 + tt) * HSn + h];
    }

    // ---- precompute per-thread staging addresses (4 chunks of 16B) ----
    const float* srel_c[4];
    uint32_t sdst_c[4];
#pragma unroll
    for (int c = 0; c < 4; ++c) {
        int idx = tid + c * 512;
        int hh = idx & 7, v = (idx >> 3) & 31, tt = idx >> 8;
        srel_c[c] = rel + ((size_t)(t0 + tt) * Tn + vbase + v) * HSn + hh * 4;
        sdst_c[c] = smem0 + (uint32_t)((((tt * 8 + hh) * 32) + (v ^ hh)) << 4);
    }

    float m[4], l[4], oa0[4], oa1[4];
#pragma unroll
    for (int j = 0; j < 4; ++j) { m[j] = -1e30f; l[j] = 0.f; oa0[j] = 0.f; oa1[j] = 0.f; }

    const float*  vbp = g_v + (size_t)b * Tn * HSn;
    const float4* kb  = ((const float4*)g_k4) + (size_t)b * 16 * Tn;
    float* spw = smf + (SP_OFF >> 2) + w * 4 * 32;

    // issue stage 0
    {
        size_t foff = 0;  // tile 0, half 0
#pragma unroll
        for (int c = 0; c < 4; ++c) cp_async16(sdst_c[c], srel_c[c] + foff);
        asm volatile("cp.async.commit_group;" ::: "memory");
    }

    ull s2[4];
    for (int s = 0; s < NSTG; ++s) {
        if (s + 1 < NSTG) {
            int tile1 = (s + 1) >> 1, half1 = (s + 1) & 1;
            size_t foff = (size_t)tile1 * (VT * HSn) + half1 * 32;
            uint32_t bofs = (uint32_t)(((s + 1) & 1) * SBUF_BYTES);
#pragma unroll
            for (int c = 0; c < 4; ++c) cp_async16(sdst_c[c] + bofs, srel_c[c] + foff);
            asm volatile("cp.async.commit_group;" ::: "memory");
            asm volatile("cp.async.wait_group 1;" ::: "memory");
        } else {
            asm volatile("cp.async.wait_group 0;" ::: "memory");
        }
        __syncthreads();

        const int tile = s >> 1, half = s & 1;
        const int v0g  = vbase + tile * VT;
        const uint32_t relb = smem0 + (uint32_t)((s & 1) * SBUF_BYTES);

        if (half == 0) {
#pragma unroll
            for (int r = 0; r < 4; ++r) s2[r] = 0ull;
        }

        // ---- Phase A: scores, f32x2, wide loads ----
#pragma unroll
        for (int hh = 0; hh < 8; ++hh) {
            const int hg = half * 8 + hh;
            ull k2a, k2b;
            ldg_v2(k2a, k2b, kb + (size_t)hg * Tn + v0g + lane);
            const uint32_t rbase = relb + (uint32_t)((hh * 32 + (lane ^ hh)) << 4);
            const uint32_t qbase = squ + (uint32_t)(((b * TQ + th4) * HSn + hg * 4) << 2);
#pragma unroll
            for (int r = 0; r < 4; ++r) {
                ull r2a, r2b, q2a, q2b;
                lds_v2(r2a, r2b, rbase + (uint32_t)(((th4 + r) * 8 * 32) << 4));
                lds_v2(q2a, q2b, qbase + (uint32_t)((r * HSn) << 2));
                s2[r] = fma2(q2a, add2(k2a, r2a), s2[r]);
                s2[r] = fma2(q2b, add2(k2b, r2b), s2[r]);
            }
        }

        if (half == 1) {
            // ---- Phase B: online softmax (warp owns full rows) ----
#pragma unroll
            for (int r = 0; r < 4; ++r) {
                float xa, xb;
                unpack2(xa, xb, s2[r]);
                float sv = xa + xb;
                float mt = sv;
#pragma unroll
                for (int o = 16; o > 0; o >>= 1)
                    mt = fmaxf(mt, __shfl_xor_sync(0xffffffffu, mt, o));
                float mn = fmaxf(m[r], mt);
                float sc = __expf(m[r] - mn);
                float p  = __expf(sv - mn);
                m[r] = mn;
                l[r] = l[r] * sc + p;
                oa0[r] *= sc; oa1[r] *= sc;
                spw[r * 32 + lane] = p;
            }
            __syncwarp();

            // ---- Phase C: PV, lanes over h ----
#pragma unroll
            for (int vq = 0; vq < VT; vq += 4) {
                float4 p0 = *(const float4*)(spw + 0 * 32 + vq);
                float4 p1 = *(const float4*)(spw + 1 * 32 + vq);
                float4 p2 = *(const float4*)(spw + 2 * 32 + vq);
                float4 p3 = *(const float4*)(spw + 3 * 32 + vq);
                const float* pa0 = (const float*)&p0;
                const float* pa1 = (const float*)&p1;
                const float* pa2 = (const float*)&p2;
                const float* pa3 = (const float*)&p3;
#pragma unroll
                for (int i = 0; i < 4; ++i) {
                    const float* vr = vbp + (size_t)(v0g + vq + i) * HSn;
                    float ve0 = __ldg(vr + lane);
                    float ve1 = __ldg(vr + lane + 32);
                    oa0[0] = fmaf(pa0[i], ve0, oa0[0]); oa1[0] = fmaf(pa0[i], ve1, oa1[0]);
                    oa0[1] = fmaf(pa1[i], ve0, oa0[1]); oa1[1] = fmaf(pa1[i], ve1, oa1[1]);
                    oa0[2] = fmaf(pa2[i], ve0, oa0[2]); oa1[2] = fmaf(pa2[i], ve1, oa1[2]);
                    oa0[3] = fmaf(pa3[i], ve0, oa0[3]); oa1[3] = fmaf(pa3[i], ve1, oa1[3]);
                }
            }
            __syncwarp();
        }
        __syncthreads();   // all warps done with relb before it is re-filled
    }

    // ---- write unnormalized partials ----
    const int sidx = blockIdx.y;
#pragma unroll
    for (int r = 0; r < 4; ++r) {
        float lt = l[r];
#pragma unroll
        for (int o = 16; o > 0; o >>= 1)
            lt += __shfl_xor_sync(0xffffffffu, lt, o);
        int row = b * Tn + t0 + th4 + r;
        size_t o0 = (size_t)row * HSn;
        g_po[sidx][o0 + lane]      = oa0[r];
        g_po[sidx][o0 + lane + 32] = oa1[r];
        if (lane == 0) { g_pm[sidx][row] = m[r]; g_pl[sidx][row] = lt; }
    }
}

// ---------------------------------------------------------------------------
// K3: merge SPLIT partials -> normalized output
// ---------------------------------------------------------------------------
__global__ __launch_bounds__(256)
void merge_kernel(float* __restrict__ out)
{
    int idx = blockIdx.x * 256 + threadIdx.x;
    int row = idx >> 6;
    float M = g_pm[0][row];
#pragma unroll
    for (int s = 1; s < SPLIT; ++s) M = fmaxf(M, g_pm[s][row]);
    float denom = 0.f, acc = 0.f;
#pragma unroll
    for (int s = 0; s < SPLIT; ++s) {
        float a = __expf(g_pm[s][row] - M);
        denom += a * g_pl[s][row];
        acc   += a * g_po[s][idx];
    }
    out[idx] = acc / denom;
}

// ---------------------------------------------------------------------------
extern "C" void kernel_launch(void* const* d_in, const int* in_sizes, int n_in,
                              void* d_out, int out_size)
{
    const float* x   = (const float*)d_in[0];
    const float* Wk  = (const float*)d_in[1];
    const float* bk  = (const float*)d_in[2];
    const float* Wq  = (const float*)d_in[3];
    const float* bq  = (const float*)d_in[4];
    const float* Wv  = (const float*)d_in[5];
    const float* bv  = (const float*)d_in[6];
    const float* rel = (const float*)d_in[7];
    float* out = (float*)d_out;

    cudaFuncSetAttribute(attn_kernel,
                         cudaFuncAttributeMaxDynamicSharedMemorySize,
                         ATTN_SMEM_BYTES);

    proj_kernel<<<(Bn * Tn) / 32, 256>>>(x, Wk, bk, Wq, bq, Wv, bv);
    attn_kernel<<<dim3(Tn / TQ, SPLIT), 512, ATTN_SMEM_BYTES>>>(rel);
    merge_kernel<<<(Bn * Tn * HSn) / 256, 256>>>(out);
}

// round 6
// speedup vs baseline: 1.2680x; 1.0173x over previous
#include <cuda_runtime.h>
#include <cstdint>
#include <cstddef>

typedef unsigned long long ull;

#define Bn 8
#define Tn 2048
#define Dn 1024
#define HSn 64
#define TQ 8
#define VT 32
#define SPLIT 4
#define VLEN (Tn / SPLIT)          // 512
#define NTILE (VLEN / VT)          // 16
#define NSTG (NTILE * 2)           // 32 stages (tile x h-half)

// Scratch (allocation-free rule: __device__ globals)
__device__ float g_q [(size_t)Bn * Tn * HSn];            // [b][t][h]
__device__ float g_k4[(size_t)Bn * 16 * Tn * 4];         // [b][hg(16)][t][4], pre-scaled by 8
__device__ float g_v [(size_t)Bn * Tn * HSn];            // [b][t][h]
__device__ float g_po[SPLIT][(size_t)Bn * Tn * HSn];
__device__ float g_pm[SPLIT][Bn * Tn];
__device__ float g_pl[SPLIT][Bn * Tn];

// ---- f32x2 + wide-load helpers --------------------------------------------
__device__ __forceinline__ ull pack2(float a, float b) {
    ull r; asm("mov.b64 %0, {%1, %2};" : "=l"(r) : "f"(a), "f"(b)); return r;
}
__device__ __forceinline__ ull add2(ull a, ull b) {
    ull r; asm("add.rn.f32x2 %0, %1, %2;" : "=l"(r) : "l"(a), "l"(b)); return r;
}
__device__ __forceinline__ ull mul2(ull a, ull b) {
    ull r; asm("mul.rn.f32x2 %0, %1, %2;" : "=l"(r) : "l"(a), "l"(b)); return r;
}
__device__ __forceinline__ ull fma2(ull a, ull b, ull c) {
    ull r; asm("fma.rn.f32x2 %0, %1, %2, %3;" : "=l"(r) : "l"(a), "l"(b), "l"(c)); return r;
}
__device__ __forceinline__ void unpack2(float& lo, float& hi, ull v) {
    asm("mov.b64 {%0, %1}, %2;" : "=f"(lo), "=f"(hi) : "l"(v));
}
__device__ __forceinline__ void lds_v2(ull& a, ull& b, uint32_t addr) {
    asm volatile("ld.shared.v2.b64 {%0, %1}, [%2];" : "=l"(a), "=l"(b) : "r"(addr));
}
__device__ __forceinline__ ull lds64(uint32_t addr) {
    ull r; asm volatile("ld.shared.b64 %0, [%1];" : "=l"(r) : "r"(addr)); return r;
}
__device__ __forceinline__ void ldg_v2(ull& a, ull& b, const void* p) {
    asm volatile("ld.global.nc.v2.b64 {%0, %1}, [%2];" : "=l"(a), "=l"(b) : "l"(p));
}
__device__ __forceinline__ ull ldg64(const void* p) {
    ull r; asm volatile("ld.global.nc.b64 %0, [%1];" : "=l"(r) : "l"(p)); return r;
}
__device__ __forceinline__ void sts_dup(uint32_t addr, float p) {
    asm volatile("st.shared.v2.f32 [%0], {%1, %1};" :: "r"(addr), "f"(p) : "memory");
}
__device__ __forceinline__ void cp_async16(uint32_t dst, const void* src) {
    asm volatile("cp.async.cg.shared.global [%0], [%1], 16;" :: "r"(dst), "l"(src) : "memory");
}

// ---------------------------------------------------------------------------
// K1: fused QKV projection.
// W staged as float2 col-pairs (c, c+96); x staged pre-duplicated (x,x).
// Per k: 2 lds_v2 (x-dup, bcast) + 3 LDS.64 (w-pair) + 12 fma2.
// ---------------------------------------------------------------------------
__global__ __launch_bounds__(256, 3)
void proj_kernel(const float* __restrict__ x,
                 const float* __restrict__ Wk, const float* __restrict__ bk,
                 const float* __restrict__ Wq, const float* __restrict__ bq,
                 const float* __restrict__ Wv, const float* __restrict__ bv)
{
    __shared__ float2 xs2[64 * 36];   // [k][tok'] dup pairs, tok' = tok ^ ((k&7)<<2)
    __shared__ float2 ws2[64 * 96];   // [k][c'] pairs (c, c+96), c' = c ^ (k&31)

    const int tid  = threadIdx.x;
    const int tok0 = blockIdx.x * 32;
    const int cl   = tid & 31;
    const int tr   = (tid >> 5) << 2;

    const uint32_t xs2u = (uint32_t)__cvta_generic_to_shared(xs2);
    const uint32_t ws2u = (uint32_t)__cvta_generic_to_shared(ws2);

    ull acc2[4][3];
#pragma unroll
    for (int i = 0; i < 4; ++i)
#pragma unroll
        for (int j = 0; j < 3; ++j) acc2[i][j] = 0ull;

    for (int k0 = 0; k0 < Dn; k0 += 64) {
        __syncthreads();
        // stage x duplicated: k-fast for coalesced reads
        for (int idx = tid; idx < 32 * 64; idx += 256) {
            int k = idx & 63, tk = idx >> 6;
            float xv = x[(size_t)(tok0 + tk) * Dn + k0 + k];
            xs2[k * 36 + (tk ^ ((k & 7) << 2))] = make_float2(xv, xv);
        }
        // stage W col-pairs: k-fast, swizzled
        for (int idx = tid; idx < 96 * 64; idx += 256) {
            int k = idx & 63, c = idx >> 6;   // c in 0..95
            const float* r0 = (c < 64)  ? (Wk + (size_t)c * Dn)
                                        : (Wq + (size_t)(c - 64) * Dn);
            int c2 = c + 96;                  // 96..191
            const float* r1 = (c2 < 128) ? (Wq + (size_t)(c2 - 64) * Dn)
                                         : (Wv + (size_t)(c2 - 128) * Dn);
            ws2[k * 96 + (c ^ (k & 31))] = make_float2(r0[k0 + k], r1[k0 + k]);
        }
        __syncthreads();

#pragma unroll 8
        for (int k = 0; k < 64; ++k) {
            ull xd0, xd1, xd2, xd3;
            uint32_t xb = xs2u + (uint32_t)((k * 36 + (tr ^ ((k & 7) << 2))) * 8);
            lds_v2(xd0, xd1, xb);
            lds_v2(xd2, xd3, xb + 16);
#pragma unroll
            for (int j = 0; j < 3; ++j) {
                ull w2 = lds64(ws2u +
                    (uint32_t)((k * 96 + ((cl + 32 * j) ^ (k & 31))) * 8));
                acc2[0][j] = fma2(xd0, w2, acc2[0][j]);
                acc2[1][j] = fma2(xd1, w2, acc2[1][j]);
                acc2[2][j] = fma2(xd2, w2, acc2[2][j]);
                acc2[3][j] = fma2(xd3, w2, acc2[3][j]);
            }
        }
    }

    // write results: acc2[i][j] = (col = cl+32j, col+96)
#pragma unroll
    for (int i = 0; i < 4; ++i) {
        int tokg = tok0 + tr + i;
        int b = tokg >> 11;
        int t = tokg & (Tn - 1);
#pragma unroll
        for (int j = 0; j < 3; ++j) {
            float a0, a1;
            unpack2(a0, a1, acc2[i][j]);
            int cols[2] = { cl + 32 * j, cl + 32 * j + 96 };
            float vals[2] = { a0, a1 };
#pragma unroll
            for (int u = 0; u < 2; ++u) {
                int col = cols[u];
                float av = vals[u];
                if (col < 64) {
                    float r = av + bk[col];
                    g_k4[(((size_t)(b * 16 + (col >> 2)) * Tn + t) << 2) + (col & 3)]
                        = 8.0f * r;
                } else if (col < 128) {
                    int h = col - 64;
                    g_q[(size_t)tokg * HSn + h] = av + bq[h];
                } else {
                    int h = col - 128;
                    g_v[(size_t)tokg * HSn + h] = av + bv[h];
                }
            }
        }
    }
}

// ---------------------------------------------------------------------------
// K2: fused attention. 256 threads = 8 warps, warp = batch, 8 rows each.
// 2 CTAs/SM (independent barrier domains). cp.async ping-pong h-half stages.
// Phase A f32x2 over h-pairs; PV with duplicated-p broadcast + packed fma2.
// ---------------------------------------------------------------------------
#define SBUF_BYTES 32768                       // 8tt x 8hg x 32v x 16B
#define SQ_OFF  (2 * SBUF_BYTES)               // 65536
#define SPD_OFF (SQ_OFF + 16384)               // q: [b][hg16][tt] float4 = 16KB
#define ATTN_SMEM_BYTES (SPD_OFF + 16384)      // pdup: 8w x 8r x 32v x 8B = 98304

__global__ __launch_bounds__(256, 2)
void attn_kernel(const float* __restrict__ rel)
{
    extern __shared__ float smf[];
    const uint32_t smem0 = (uint32_t)__cvta_generic_to_shared(smf);
    const uint32_t squ   = smem0 + SQ_OFF;

    const int tid  = threadIdx.x;
    const int w    = tid >> 5;      // warp = batch
    const int lane = tid & 31;      // lane = v within tile
    const int t0   = blockIdx.x * TQ;
    const int vbase = blockIdx.y * VLEN;

    // ---- stage q: [b][hg][tt] float4 (published by first stage barrier) ----
    {
        float4* sq4 = (float4*)(smf + (SQ_OFF >> 2));
        for (int idx = tid; idx < 1024; idx += 256) {
            int hg = idx & 15, tt = (idx >> 4) & 7, b = idx >> 7;
            sq4[(b * 16 + hg) * 8 + tt] =
                *(const float4*)(g_q + ((size_t)b * Tn + t0 + tt) * HSn + hg * 4);
        }
    }

    // ---- per-thread cp.async chunk map: idx = (tt*32+v)*8 + hgl ----
    const float* srel_c[8];
    uint32_t sdst_c[8];
#pragma unroll
    for (int c = 0; c < 8; ++c) {
        int idx = tid + c * 256;
        int hgl = idx & 7, v = (idx >> 3) & 31, tt = idx >> 8;
        srel_c[c] = rel + ((size_t)(t0 + tt) * Tn + vbase + v) * HSn + hgl * 4;
        sdst_c[c] = smem0 + (uint32_t)((((tt * 8 + hgl) * 32) + (v ^ hgl)) << 4);
    }

    float m[8], l[8];
    ull oa2[8];
#pragma unroll
    for (int r = 0; r < 8; ++r) { m[r] = -1e30f; l[r] = 0.f; oa2[r] = 0ull; }

    const float*  vb  = g_v + (size_t)w * Tn * HSn;
    const float4* kb4 = ((const float4*)g_k4) + (size_t)w * 16 * Tn;
    const uint32_t spd = smem0 + SPD_OFF + (uint32_t)(w * 8 * 32 * 8);

    // prologue: stage 0
#pragma unroll
    for (int c = 0; c < 8; ++c) cp_async16(sdst_c[c], srel_c[c]);
    asm volatile("cp.async.commit_group;" ::: "memory");

    ull s2h[8];
    for (int s = 0; s < NSTG; ++s) {
        if (s + 1 < NSTG) {
            // src advance: tile*2048 + half*32 floats
            size_t foff = (size_t)((s + 1) >> 1) * 2048 + ((s + 1) & 1) * 32;
            uint32_t bofs = (uint32_t)(((s + 1) & 1) * SBUF_BYTES);
#pragma unroll
            for (int c = 0; c < 8; ++c) cp_async16(sdst_c[c] + bofs, srel_c[c] + foff);
            asm volatile("cp.async.commit_group;" ::: "memory");
            asm volatile("cp.async.wait_group 1;" ::: "memory");
        } else {
            asm volatile("cp.async.wait_group 0;" ::: "memory");
        }
        __syncthreads();

        const int tile = s >> 1, half = s & 1;
        const int v0g  = vbase + tile * VT;
        const uint32_t relb = smem0 + (uint32_t)((s & 1) * SBUF_BYTES);

        if (half == 0) {
#pragma unroll
            for (int r = 0; r < 8; ++r) s2h[r] = 0ull;
        }

        // ---- Phase A: packed-h scores ----
#pragma unroll
        for (int hgl = 0; hgl < 8; ++hgl) {
            const int hg = half * 8 + hgl;
            ull k2a, k2b;
            ldg_v2(k2a, k2b, kb4 + (size_t)hg * Tn + v0g + lane);
            const uint32_t rb = relb + (uint32_t)(((hgl * 32) + (lane ^ hgl)) << 4);
            const uint32_t qb = squ + (uint32_t)(((w * 16 + hg) * 8) << 4);
#pragma unroll
            for (int r = 0; r < 8; ++r) {
                ull r2a, r2b, q2a, q2b;
                lds_v2(r2a, r2b, rb + (uint32_t)((r * 8 * 32) << 4));
                lds_v2(q2a, q2b, qb + (uint32_t)(r << 4));
                s2h[r] = fma2(q2a, add2(k2a, r2a), s2h[r]);
                s2h[r] = fma2(q2b, add2(k2b, r2b), s2h[r]);
            }
        }

        if (half == 1) {
            // ---- Phase B: online softmax (warp owns full rows) ----
#pragma unroll
            for (int r = 0; r < 8; ++r) {
                float xa, xb;
                unpack2(xa, xb, s2h[r]);
                float sv = xa + xb;
                float mt = sv;
#pragma unroll
                for (int o = 16; o > 0; o >>= 1)
                    mt = fmaxf(mt, __shfl_xor_sync(0xffffffffu, mt, o));
                float mn = fmaxf(m[r], mt);
                float sc = __expf(m[r] - mn);
                float p  = __expf(sv - mn);
                m[r] = mn;
                l[r] = l[r] * sc + p;
                oa2[r] = mul2(oa2[r], pack2(sc, sc));
                sts_dup(spd + (uint32_t)((r * 32 + lane) * 8), p);
            }
            __syncwarp();

            // ---- Phase C: PV, packed h-pairs, duplicated-p broadcast ----
#pragma unroll 4
            for (int vq = 0; vq < VT; vq += 2) {
                ull v2_0 = ldg64(vb + (size_t)(v0g + vq) * HSn + 2 * lane);
                ull v2_1 = ldg64(vb + (size_t)(v0g + vq + 1) * HSn + 2 * lane);
#pragma unroll
                for (int r = 0; r < 8; ++r) {
                    ull pd0, pd1;
                    lds_v2(pd0, pd1, spd + (uint32_t)((r * 32 + vq) * 8));
                    oa2[r] = fma2(pd0, v2_0, oa2[r]);
                    oa2[r] = fma2(pd1, v2_1, oa2[r]);
                }
            }
            __syncwarp();
        }
        __syncthreads();   // all warps done with relb before re-fill
    }

    // ---- write unnormalized partials ----
    const int sidx = blockIdx.y;
#pragma unroll
    for (int r = 0; r < 8; ++r) {
        float lt = l[r];
#pragma unroll
        for (int o = 16; o > 0; o >>= 1)
            lt += __shfl_xor_sync(0xffffffffu, lt, o);
        int row = w * Tn + t0 + r;
        float o0, o1;
        unpack2(o0, o1, oa2[r]);
        ((float2*)(g_po[sidx] + (size_t)row * HSn))[lane] = make_float2(o0, o1);
        if (lane == 0) { g_pm[sidx][row] = m[r]; g_pl[sidx][row] = lt; }
    }
}

// ---------------------------------------------------------------------------
// K3: merge SPLIT partials -> normalized output
// ---------------------------------------------------------------------------
__global__ __launch_bounds__(256)
void merge_kernel(float* __restrict__ out)
{
    int idx = blockIdx.x * 256 + threadIdx.x;
    int row = idx >> 6;
    float M = g_pm[0][row];
#pragma unroll
    for (int s = 1; s < SPLIT; ++s) M = fmaxf(M, g_pm[s][row]);
    float denom = 0.f, acc = 0.f;
#pragma unroll
    for (int s = 0; s < SPLIT; ++s) {
        float a = __expf(g_pm[s][row] - M);
        denom += a * g_pl[s][row];
        acc   += a * g_po[s][idx];
    }
    out[idx] = acc / denom;
}

// ---------------------------------------------------------------------------
extern "C" void kernel_launch(void* const* d_in, const int* in_sizes, int n_in,
                              void* d_out, int out_size)
{
    const float* x   = (const float*)d_in[0];
    const float* Wk  = (const float*)d_in[1];
    const float* bk  = (const float*)d_in[2];
    const float* Wq  = (const float*)d_in[3];
    const float* bq  = (const float*)d_in[4];
    const float* Wv  = (const float*)d_in[5];
    const float* bv  = (const float*)d_in[6];
    const float* rel = (const float*)d_in[7];
    float* out = (float*)d_out;

    cudaFuncSetAttribute(attn_kernel,
                         cudaFuncAttributeMaxDynamicSharedMemorySize,
                         ATTN_SMEM_BYTES);

    proj_kernel<<<(Bn * Tn) / 32, 256>>>(x, Wk, bk, Wq, bq, Wv, bv);
    attn_kernel<<<dim3(Tn / TQ, SPLIT), 256, ATTN_SMEM_BYTES>>>(rel);
    merge_kernel<<<(Bn * Tn * HSn) / 256, 256>>>(out);
}

// round 7
// speedup vs baseline: 1.5070x; 1.1885x over previous
#include <cuda_runtime.h>
#include <cstdint>
#include <cstddef>

typedef unsigned long long ull;

#define Bn 8
#define Tn 2048
#define Dn 1024
#define HSn 64
#define TQ 8
#define VT 32
#define SPLIT 4
#define VLEN (Tn / SPLIT)          // 512
#define NTILE (VLEN / VT)          // 16
#define NSTG (NTILE * 2)           // 32 stages (tile x h-half)

// Scratch (allocation-free rule: __device__ globals)
__device__ float g_q [(size_t)Bn * Tn * HSn];            // [b][t][h]
__device__ float g_k4[(size_t)Bn * 16 * Tn * 4];         // [b][hg(16)][t][4], pre-scaled by 8
__device__ float g_v [(size_t)Bn * Tn * HSn];            // [b][t][h]
__device__ float g_po[SPLIT][(size_t)Bn * Tn * HSn];
__device__ float g_pm[SPLIT][Bn * Tn];
__device__ float g_pl[SPLIT][Bn * Tn];

// ---- f32x2 + wide-load helpers --------------------------------------------
__device__ __forceinline__ ull pack2(float a, float b) {
    ull r; asm("mov.b64 %0, {%1, %2};" : "=l"(r) : "f"(a), "f"(b)); return r;
}
__device__ __forceinline__ ull add2(ull a, ull b) {
    ull r; asm("add.rn.f32x2 %0, %1, %2;" : "=l"(r) : "l"(a), "l"(b)); return r;
}
__device__ __forceinline__ ull mul2(ull a, ull b) {
    ull r; asm("mul.rn.f32x2 %0, %1, %2;" : "=l"(r) : "l"(a), "l"(b)); return r;
}
__device__ __forceinline__ ull fma2(ull a, ull b, ull c) {
    ull r; asm("fma.rn.f32x2 %0, %1, %2, %3;" : "=l"(r) : "l"(a), "l"(b), "l"(c)); return r;
}
__device__ __forceinline__ void unpack2(float& lo, float& hi, ull v) {
    asm("mov.b64 {%0, %1}, %2;" : "=f"(lo), "=f"(hi) : "l"(v));
}
__device__ __forceinline__ void lds_v2(ull& a, ull& b, uint32_t addr) {
    asm volatile("ld.shared.v2.b64 {%0, %1}, [%2];" : "=l"(a), "=l"(b) : "r"(addr));
}
__device__ __forceinline__ void ldg_v2(ull& a, ull& b, const void* p) {
    asm volatile("ld.global.nc.v2.b64 {%0, %1}, [%2];" : "=l"(a), "=l"(b) : "l"(p));
}
__device__ __forceinline__ ull ldg64(const void* p) {
    ull r; asm volatile("ld.global.nc.b64 %0, [%1];" : "=l"(r) : "l"(p)); return r;
}
__device__ __forceinline__ void sts_dup(uint32_t addr, float p) {
    asm volatile("st.shared.v2.f32 [%0], {%1, %1};" :: "r"(addr), "f"(p) : "memory");
}
__device__ __forceinline__ void cp_async16(uint32_t dst, const void* src) {
    asm volatile("cp.async.cg.shared.global [%0], [%1], 16;" :: "r"(dst), "l"(src) : "memory");
}

// ---------------------------------------------------------------------------
// K1: fused QKV projection (R5 version — best measured: 318us).
// Block: 32 tokens x 192 cols, 256 threads; warp lane = col, 4 tokens/thread.
// ---------------------------------------------------------------------------
__global__ __launch_bounds__(256, 3)
void proj_kernel(const float* __restrict__ x,
                 const float* __restrict__ Wk, const float* __restrict__ bk,
                 const float* __restrict__ Wq, const float* __restrict__ bq,
                 const float* __restrict__ Wv, const float* __restrict__ bv)
{
    __shared__ float xsT[64 * 36];     // [k][tok]
    __shared__ float ws[64][193];      // [k][col]

    const int tid  = threadIdx.x;
    const int tok0 = blockIdx.x * 32;
    const int cl   = tid & 31;
    const int tr   = (tid >> 5) << 2;

    const uint32_t xsT_u = (uint32_t)__cvta_generic_to_shared(xsT);

    ull acc2[2][6];
#pragma unroll
    for (int i = 0; i < 2; ++i)
#pragma unroll
        for (int j = 0; j < 6; ++j) acc2[i][j] = 0ull;

    for (int k0 = 0; k0 < Dn; k0 += 64) {
        __syncthreads();
        for (int idx = tid; idx < 32 * 64; idx += 256) {
            int k = idx & 63, tk = idx >> 6;
            xsT[k * 36 + tk] = x[(size_t)(tok0 + tk) * Dn + k0 + k];
        }
        for (int idx = tid; idx < 192 * 64; idx += 256) {
            int k = idx & 63, col = idx >> 6;
            const float* Wsrc = (col < 64) ? Wk : ((col < 128) ? Wq : Wv);
            ws[k][col] = Wsrc[(size_t)(col & 63) * Dn + k0 + k];
        }
        __syncthreads();

#pragma unroll 8
        for (int k = 0; k < 64; ++k) {
            ull x2a, x2b;
            lds_v2(x2a, x2b, xsT_u + (uint32_t)(k * 36 + tr) * 4u);
#pragma unroll
            for (int j = 0; j < 6; ++j) {
                float wv = ws[k][cl + 32 * j];
                ull wd = pack2(wv, wv);
                acc2[0][j] = fma2(x2a, wd, acc2[0][j]);
                acc2[1][j] = fma2(x2b, wd, acc2[1][j]);
            }
        }
    }

#pragma unroll
    for (int j = 0; j < 6; ++j) {
        float a[4];
        unpack2(a[0], a[1], acc2[0][j]);
        unpack2(a[2], a[3], acc2[1][j]);
        int col = cl + 32 * j;
        int h = col & 63;
#pragma unroll
        for (int i = 0; i < 4; ++i) {
            int tokg = tok0 + tr + i;
            int b = tokg >> 11;
            int t = tokg & (Tn - 1);
            if (col < 64) {
                float r = a[i] + bk[h];
                g_k4[(((size_t)(b * 16 + (h >> 2)) * Tn + t) << 2) + (h & 3)] = 8.0f * r;
            } else if (col < 128) {
                g_q[(size_t)tokg * HSn + h] = a[i] + bq[h];
            } else {
                g_v[(size_t)tokg * HSn + h] = a[i] + bv[h];
            }
        }
    }
}

// ---------------------------------------------------------------------------
// K2: fused attention. 256 threads = 8 warps, 2 CTAs/SM.
// Warp w: batch pair bp=w&3 (batches 2bp,2bp+1), row-quad rh=w>>2 (rows 4rh..).
// rel smem rows per warp = 4 (HALF of R6) — each rel tile element read 4x not 8x.
// Single barrier per stage: wait -> barrier -> issue s+1 -> compute s.
// ---------------------------------------------------------------------------
#define SBUF_BYTES 32768                       // 8tt x 8hg x 32v x 16B
#define SQ_OFF  (2 * SBUF_BYTES)               // 65536
#define SPD_OFF (SQ_OFF + 16384)               // q: [b][hg16][tt] float4 = 16KB
#define ATTN_SMEM_BYTES (SPD_OFF + 16384)      // pdup: [b][tt][32v] x 8B = 98304

__global__ __launch_bounds__(256, 2)
void attn_kernel(const float* __restrict__ rel)
{
    extern __shared__ float smf[];
    const uint32_t smem0 = (uint32_t)__cvta_generic_to_shared(smf);
    const uint32_t squ   = smem0 + SQ_OFF;

    const int tid  = threadIdx.x;
    const int w    = tid >> 5;
    const int lane = tid & 31;
    const int b0   = (w & 3) * 2;        // batch pair
    const int b1   = b0 + 1;
    const int rh4  = (w >> 2) << 2;      // row quad base (0 or 4)
    const int t0   = blockIdx.x * TQ;
    const int vbase = blockIdx.y * VLEN;

    // ---- stage q: [b][hg][tt] float4 (published by first stage barrier) ----
    {
        float4* sq4 = (float4*)(smf + (SQ_OFF >> 2));
        for (int idx = tid; idx < 1024; idx += 256) {
            int hg = idx & 15, tt = (idx >> 4) & 7, b = idx >> 7;
            sq4[(b * 16 + hg) * 8 + tt] =
                *(const float4*)(g_q + ((size_t)b * Tn + t0 + tt) * HSn + hg * 4);
        }
    }

    // ---- per-thread cp.async chunk map: idx = (tt*32+v)*8 + hgl ----
    const float* srel_c[8];
    uint32_t sdst_c[8];
#pragma unroll
    for (int c = 0; c < 8; ++c) {
        int idx = tid + c * 256;
        int hgl = idx & 7, v = (idx >> 3) & 31, tt = idx >> 8;
        srel_c[c] = rel + ((size_t)(t0 + tt) * Tn + vbase + v) * HSn + hgl * 4;
        sdst_c[c] = smem0 + (uint32_t)((((tt * 8 + hgl) * 32) + (v ^ hgl)) << 4);
    }

    float m[2][4], l[2][4];
    ull oa2[2][4];
#pragma unroll
    for (int bi = 0; bi < 2; ++bi)
#pragma unroll
        for (int r = 0; r < 4; ++r) { m[bi][r] = -1e30f; l[bi][r] = 0.f; oa2[bi][r] = 0ull; }

    const float*  vb0 = g_v + (size_t)b0 * Tn * HSn;
    const float*  vb1 = g_v + (size_t)b1 * Tn * HSn;
    const float4* kb0 = ((const float4*)g_k4) + (size_t)b0 * 16 * Tn;
    const float4* kb1 = ((const float4*)g_k4) + (size_t)b1 * 16 * Tn;
    const uint32_t spd = smem0 + SPD_OFF;   // [b][tt][v] dup pairs

    // prologue: issue stage 0
#pragma unroll
    for (int c = 0; c < 8; ++c) cp_async16(sdst_c[c], srel_c[c]);
    asm volatile("cp.async.commit_group;" ::: "memory");

    ull s2h[2][4];
    for (int s = 0; s < NSTG; ++s) {
        asm volatile("cp.async.wait_group 0;" ::: "memory");
        __syncthreads();          // publishes stage s; proves stage s-1 reads done

        if (s + 1 < NSTG) {
            size_t foff = (size_t)((s + 1) >> 1) * 2048 + ((s + 1) & 1) * 32;
            uint32_t bofs = (uint32_t)(((s + 1) & 1) * SBUF_BYTES);
#pragma unroll
            for (int c = 0; c < 8; ++c) cp_async16(sdst_c[c] + bofs, srel_c[c] + foff);
            asm volatile("cp.async.commit_group;" ::: "memory");
        }

        const int tile = s >> 1, half = s & 1;
        const int v0g  = vbase + tile * VT;
        const uint32_t relb = smem0 + (uint32_t)((s & 1) * SBUF_BYTES);

        if (half == 0) {
#pragma unroll
            for (int bi = 0; bi < 2; ++bi)
#pragma unroll
                for (int r = 0; r < 4; ++r) s2h[bi][r] = 0ull;
        }

        // ---- Phase A: packed-h scores, 2 batches x 4 rows ----
#pragma unroll
        for (int hgl = 0; hgl < 8; ++hgl) {
            const int hg = half * 8 + hgl;
            ull k0a, k0b, k1a, k1b;
            ldg_v2(k0a, k0b, kb0 + (size_t)hg * Tn + v0g + lane);
            ldg_v2(k1a, k1b, kb1 + (size_t)hg * Tn + v0g + lane);
            const uint32_t rb  = relb + (uint32_t)(((hgl * 32) + (lane ^ hgl)) << 4);
            const uint32_t qb0 = squ + (uint32_t)((((b0 * 16 + hg) * 8) + rh4) << 4);
            const uint32_t qb1 = squ + (uint32_t)((((b1 * 16 + hg) * 8) + rh4) << 4);
#pragma unroll
            for (int r = 0; r < 4; ++r) {
                ull r2a, r2b;
                lds_v2(r2a, r2b, rb + (uint32_t)((((rh4 + r) * 8 * 32)) << 4));
                ull q0a, q0b, q1a, q1b;
                lds_v2(q0a, q0b, qb0 + (uint32_t)(r << 4));
                lds_v2(q1a, q1b, qb1 + (uint32_t)(r << 4));
                s2h[0][r] = fma2(q0a, add2(k0a, r2a), s2h[0][r]);
                s2h[0][r] = fma2(q0b, add2(k0b, r2b), s2h[0][r]);
                s2h[1][r] = fma2(q1a, add2(k1a, r2a), s2h[1][r]);
                s2h[1][r] = fma2(q1b, add2(k1b, r2b), s2h[1][r]);
            }
        }

        if (half == 1) {
            // ---- Phase B: online softmax (warp owns full rows) ----
#pragma unroll
            for (int bi = 0; bi < 2; ++bi) {
                const int bb = b0 + bi;
#pragma unroll
                for (int r = 0; r < 4; ++r) {
                    float xa, xb;
                    unpack2(xa, xb, s2h[bi][r]);
                    float sv = xa + xb;
                    float mt = sv;
#pragma unroll
                    for (int o = 16; o > 0; o >>= 1)
                        mt = fmaxf(mt, __shfl_xor_sync(0xffffffffu, mt, o));
                    float mn = fmaxf(m[bi][r], mt);
                    float sc = __expf(m[bi][r] - mn);
                    float p  = __expf(sv - mn);
                    m[bi][r] = mn;
                    l[bi][r] = l[bi][r] * sc + p;
                    oa2[bi][r] = mul2(oa2[bi][r], pack2(sc, sc));
                    sts_dup(spd + (uint32_t)((((bb * 8 + rh4 + r) * 32) + lane) * 8), p);
                }
            }
            __syncwarp();

            // ---- Phase C: PV, packed h-pairs, duplicated-p broadcast ----
#pragma unroll 4
            for (int vq = 0; vq < VT; vq += 2) {
                ull va0 = ldg64(vb0 + (size_t)(v0g + vq)     * HSn + 2 * lane);
                ull va1 = ldg64(vb0 + (size_t)(v0g + vq + 1) * HSn + 2 * lane);
                ull vb_0 = ldg64(vb1 + (size_t)(v0g + vq)     * HSn + 2 * lane);
                ull vb_1 = ldg64(vb1 + (size_t)(v0g + vq + 1) * HSn + 2 * lane);
#pragma unroll
                for (int r = 0; r < 4; ++r) {
                    ull p0a, p0b, p1a, p1b;
                    lds_v2(p0a, p0b, spd + (uint32_t)((((b0 * 8 + rh4 + r) * 32) + vq) * 8));
                    lds_v2(p1a, p1b, spd + (uint32_t)((((b1 * 8 + rh4 + r) * 32) + vq) * 8));
                    oa2[0][r] = fma2(p0a, va0, oa2[0][r]);
                    oa2[0][r] = fma2(p0b, va1, oa2[0][r]);
                    oa2[1][r] = fma2(p1a, vb_0, oa2[1][r]);
                    oa2[1][r] = fma2(p1b, vb_1, oa2[1][r]);
                }
            }
            __syncwarp();
        }
    }

    // ---- write unnormalized partials ----
    const int sidx = blockIdx.y;
#pragma unroll
    for (int bi = 0; bi < 2; ++bi) {
        const int bb = b0 + bi;
#pragma unroll
        for (int r = 0; r < 4; ++r) {
            float lt = l[bi][r];
#pragma unroll
            for (int o = 16; o > 0; o >>= 1)
                lt += __shfl_xor_sync(0xffffffffu, lt, o);
            int row = bb * Tn + t0 + rh4 + r;
            float o0, o1;
            unpack2(o0, o1, oa2[bi][r]);
            ((float2*)(g_po[sidx] + (size_t)row * HSn))[lane] = make_float2(o0, o1);
            if (lane == 0) { g_pm[sidx][row] = m[bi][r]; g_pl[sidx][row] = lt; }
        }
    }
}

// ---------------------------------------------------------------------------
// K3: merge SPLIT partials -> normalized output
// ---------------------------------------------------------------------------
__global__ __launch_bounds__(256)
void merge_kernel(float* __restrict__ out)
{
    int idx = blockIdx.x * 256 + threadIdx.x;
    int row = idx >> 6;
    float M = g_pm[0][row];
#pragma unroll
    for (int s = 1; s < SPLIT; ++s) M = fmaxf(M, g_pm[s][row]);
    float denom = 0.f, acc = 0.f;
#pragma unroll
    for (int s = 0; s < SPLIT; ++s) {
        float a = __expf(g_pm[s][row] - M);
        denom += a * g_pl[s][row];
        acc   += a * g_po[s][idx];
    }
    out[idx] = acc / denom;
}

// ---------------------------------------------------------------------------
extern "C" void kernel_launch(void* const* d_in, const int* in_sizes, int n_in,
                              void* d_out, int out_size)
{
    const float* x   = (const float*)d_in[0];
    const float* Wk  = (const float*)d_in[1];
    const float* bk  = (const float*)d_in[2];
    const float* Wq  = (const float*)d_in[3];
    const float* bq  = (const float*)d_in[4];
    const float* Wv  = (const float*)d_in[5];
    const float* bv  = (const float*)d_in[6];
    const float* rel = (const float*)d_in[7];
    float* out = (float*)d_out;

    cudaFuncSetAttribute(attn_kernel,
                         cudaFuncAttributeMaxDynamicSharedMemorySize,
                         ATTN_SMEM_BYTES);

    proj_kernel<<<(Bn * Tn) / 32, 256>>>(x, Wk, bk, Wq, bq, Wv, bv);
    attn_kernel<<<dim3(Tn / TQ, SPLIT), 256, ATTN_SMEM_BYTES>>>(rel);
    merge_kernel<<<(Bn * Tn * HSn) / 256, 256>>>(out);
}

// round 8
// speedup vs baseline: 1.5266x; 1.0129x over previous
#include <cuda_runtime.h>
#include <cstdint>
#include <cstddef>

typedef unsigned long long ull;

#define Bn 8
#define Tn 2048
#define Dn 1024
#define HSn 64
#define TQ 8
#define VT 32
#define SPLIT 8
#define VLEN (Tn / SPLIT)          // 256
#define NTILE (VLEN / VT)          // 8
#define NSTG (NTILE * 2)           // 16 stages (tile x h-half)

// Scratch (allocation-free rule: __device__ globals)
__device__ float g_q [(size_t)Bn * Tn * HSn];            // [b][t][h]
__device__ float g_k4[(size_t)Bn * 16 * Tn * 4];         // [b][hg(16)][t][4], pre-scaled by 8
__device__ float g_v [(size_t)Bn * Tn * HSn];            // [b][t][h]
__device__ float g_po[SPLIT][(size_t)Bn * Tn * HSn];
__device__ float g_pm[SPLIT][Bn * Tn];
__device__ float g_pl[SPLIT][Bn * Tn];

// ---- f32x2 + wide-load helpers --------------------------------------------
__device__ __forceinline__ ull pack2(float a, float b) {
    ull r; asm("mov.b64 %0, {%1, %2};" : "=l"(r) : "f"(a), "f"(b)); return r;
}
__device__ __forceinline__ ull add2(ull a, ull b) {
    ull r; asm("add.rn.f32x2 %0, %1, %2;" : "=l"(r) : "l"(a), "l"(b)); return r;
}
__device__ __forceinline__ ull mul2(ull a, ull b) {
    ull r; asm("mul.rn.f32x2 %0, %1, %2;" : "=l"(r) : "l"(a), "l"(b)); return r;
}
__device__ __forceinline__ ull fma2(ull a, ull b, ull c) {
    ull r; asm("fma.rn.f32x2 %0, %1, %2, %3;" : "=l"(r) : "l"(a), "l"(b), "l"(c)); return r;
}
__device__ __forceinline__ void unpack2(float& lo, float& hi, ull v) {
    asm("mov.b64 {%0, %1}, %2;" : "=f"(lo), "=f"(hi) : "l"(v));
}
__device__ __forceinline__ void lds_v2(ull& a, ull& b, uint32_t addr) {
    asm volatile("ld.shared.v2.b64 {%0, %1}, [%2];" : "=l"(a), "=l"(b) : "r"(addr));
}
__device__ __forceinline__ void ldg_v2(ull& a, ull& b, const void* p) {
    asm volatile("ld.global.nc.v2.b64 {%0, %1}, [%2];" : "=l"(a), "=l"(b) : "l"(p));
}
__device__ __forceinline__ ull ldg64(const void* p) {
    ull r; asm volatile("ld.global.nc.b64 %0, [%1];" : "=l"(r) : "l"(p)); return r;
}
__device__ __forceinline__ void sts_dup(uint32_t addr, float p) {
    asm volatile("st.shared.v2.f32 [%0], {%1, %1};" :: "r"(addr), "f"(p) : "memory");
}
__device__ __forceinline__ void cp_async16(uint32_t dst, const void* src) {
    asm volatile("cp.async.cg.shared.global [%0], [%1], 16;" :: "r"(dst), "l"(src) : "memory");
}

// ---------------------------------------------------------------------------
// K1: fused QKV projection (R5 version — measured best: ~307us). UNCHANGED.
// ---------------------------------------------------------------------------
__global__ __launch_bounds__(256, 3)
void proj_kernel(const float* __restrict__ x,
                 const float* __restrict__ Wk, const float* __restrict__ bk,
                 const float* __restrict__ Wq, const float* __restrict__ bq,
                 const float* __restrict__ Wv, const float* __restrict__ bv)
{
    __shared__ float xsT[64 * 36];     // [k][tok]
    __shared__ float ws[64][193];      // [k][col]

    const int tid  = threadIdx.x;
    const int tok0 = blockIdx.x * 32;
    const int cl   = tid & 31;
    const int tr   = (tid >> 5) << 2;

    const uint32_t xsT_u = (uint32_t)__cvta_generic_to_shared(xsT);

    ull acc2[2][6];
#pragma unroll
    for (int i = 0; i < 2; ++i)
#pragma unroll
        for (int j = 0; j < 6; ++j) acc2[i][j] = 0ull;

    for (int k0 = 0; k0 < Dn; k0 += 64) {
        __syncthreads();
        for (int idx = tid; idx < 32 * 64; idx += 256) {
            int k = idx & 63, tk = idx >> 6;
            xsT[k * 36 + tk] = x[(size_t)(tok0 + tk) * Dn + k0 + k];
        }
        for (int idx = tid; idx < 192 * 64; idx += 256) {
            int k = idx & 63, col = idx >> 6;
            const float* Wsrc = (col < 64) ? Wk : ((col < 128) ? Wq : Wv);
            ws[k][col] = Wsrc[(size_t)(col & 63) * Dn + k0 + k];
        }
        __syncthreads();

#pragma unroll 8
        for (int k = 0; k < 64; ++k) {
            ull x2a, x2b;
            lds_v2(x2a, x2b, xsT_u + (uint32_t)(k * 36 + tr) * 4u);
#pragma unroll
            for (int j = 0; j < 6; ++j) {
                float wv = ws[k][cl + 32 * j];
                ull wd = pack2(wv, wv);
                acc2[0][j] = fma2(x2a, wd, acc2[0][j]);
                acc2[1][j] = fma2(x2b, wd, acc2[1][j]);
            }
        }
    }

#pragma unroll
    for (int j = 0; j < 6; ++j) {
        float a[4];
        unpack2(a[0], a[1], acc2[0][j]);
        unpack2(a[2], a[3], acc2[1][j]);
        int col = cl + 32 * j;
        int h = col & 63;
#pragma unroll
        for (int i = 0; i < 4; ++i) {
            int tokg = tok0 + tr + i;
            int b = tokg >> 11;
            int t = tokg & (Tn - 1);
            if (col < 64) {
                float r = a[i] + bk[h];
                g_k4[(((size_t)(b * 16 + (h >> 2)) * Tn + t) << 2) + (h & 3)] = 8.0f * r;
            } else if (col < 128) {
                g_q[(size_t)tokg * HSn + h] = a[i] + bq[h];
            } else {
                g_v[(size_t)tokg * HSn + h] = a[i] + bv[h];
            }
        }
    }
}

// ---------------------------------------------------------------------------
// K2: fused attention. 256 threads = 8 warps, 2 CTAs/SM.
// Warp w: batch pair b0=2*(w&3), rows rh4=4*(w>>2).
// R8: software-pipelined k (phase A) and v (PV) register prefetch; SPLIT=8.
// ---------------------------------------------------------------------------
#define SBUF_BYTES 32768                       // 8tt x 8hg x 32v x 16B
#define SQ_OFF  (2 * SBUF_BYTES)               // 65536
#define SPD_OFF (SQ_OFF + 16384)               // q: [b][hg16][tt] float4 = 16KB
#define ATTN_SMEM_BYTES (SPD_OFF + 16384)      // pdup: [b][tt][32v] x 8B = 98304

__global__ __launch_bounds__(256, 2)
void attn_kernel(const float* __restrict__ rel)
{
    extern __shared__ float smf[];
    const uint32_t smem0 = (uint32_t)__cvta_generic_to_shared(smf);
    const uint32_t squ   = smem0 + SQ_OFF;

    const int tid  = threadIdx.x;
    const int w    = tid >> 5;
    const int lane = tid & 31;
    const int b0   = (w & 3) * 2;
    const int b1   = b0 + 1;
    const int rh4  = (w >> 2) << 2;
    const int t0   = blockIdx.x * TQ;
    const int vbase = blockIdx.y * VLEN;

    // ---- stage q: [b][hg][tt] float4 (published by first stage barrier) ----
    {
        float4* sq4 = (float4*)(smf + (SQ_OFF >> 2));
        for (int idx = tid; idx < 1024; idx += 256) {
            int hg = idx & 15, tt = (idx >> 4) & 7, b = idx >> 7;
            sq4[(b * 16 + hg) * 8 + tt] =
                *(const float4*)(g_q + ((size_t)b * Tn + t0 + tt) * HSn + hg * 4);
        }
    }

    // ---- per-thread cp.async chunk map: idx = (tt*32+v)*8 + hgl ----
    const float* srel_c[8];
    uint32_t sdst_c[8];
#pragma unroll
    for (int c = 0; c < 8; ++c) {
        int idx = tid + c * 256;
        int hgl = idx & 7, v = (idx >> 3) & 31, tt = idx >> 8;
        srel_c[c] = rel + ((size_t)(t0 + tt) * Tn + vbase + v) * HSn + hgl * 4;
        sdst_c[c] = smem0 + (uint32_t)((((tt * 8 + hgl) * 32) + (v ^ hgl)) << 4);
    }

    float m[2][4], l[2][4];
    ull oa2[2][4];
#pragma unroll
    for (int bi = 0; bi < 2; ++bi)
#pragma unroll
        for (int r = 0; r < 4; ++r) { m[bi][r] = -1e30f; l[bi][r] = 0.f; oa2[bi][r] = 0ull; }

    const float*  vb0 = g_v + (size_t)b0 * Tn * HSn;
    const float*  vb1 = g_v + (size_t)b1 * Tn * HSn;
    const float4* kb0 = ((const float4*)g_k4) + (size_t)b0 * 16 * Tn;
    const float4* kb1 = ((const float4*)g_k4) + (size_t)b1 * 16 * Tn;
    const uint32_t spd = smem0 + SPD_OFF;

    // prologue: issue stage 0
#pragma unroll
    for (int c = 0; c < 8; ++c) cp_async16(sdst_c[c], srel_c[c]);
    asm volatile("cp.async.commit_group;" ::: "memory");

    ull s2h[2][4];
    for (int s = 0; s < NSTG; ++s) {
        asm volatile("cp.async.wait_group 0;" ::: "memory");
        __syncthreads();          // publishes stage s; proves stage s-1 reads done

        if (s + 1 < NSTG) {
            size_t foff = (size_t)((s + 1) >> 1) * 2048 + ((s + 1) & 1) * 32;
            uint32_t bofs = (uint32_t)(((s + 1) & 1) * SBUF_BYTES);
#pragma unroll
            for (int c = 0; c < 8; ++c) cp_async16(sdst_c[c] + bofs, srel_c[c] + foff);
            asm volatile("cp.async.commit_group;" ::: "memory");
        }

        const int tile = s >> 1, half = s & 1;
        const int v0g  = vbase + tile * VT;
        const uint32_t relb = smem0 + (uint32_t)((s & 1) * SBUF_BYTES);

        if (half == 0) {
#pragma unroll
            for (int bi = 0; bi < 2; ++bi)
#pragma unroll
                for (int r = 0; r < 4; ++r) s2h[bi][r] = 0ull;
        }

        // ---- Phase A: packed-h scores, k software-pipelined ----
        ull kc[4], kn[4];
        {
            const int hg0 = half * 8;
            ldg_v2(kc[0], kc[1], kb0 + (size_t)hg0 * Tn + v0g + lane);
            ldg_v2(kc[2], kc[3], kb1 + (size_t)hg0 * Tn + v0g + lane);
        }
#pragma unroll
        for (int hgl = 0; hgl < 8; ++hgl) {
            const int hg = half * 8 + hgl;
            if (hgl < 7) {
                ldg_v2(kn[0], kn[1], kb0 + (size_t)(hg + 1) * Tn + v0g + lane);
                ldg_v2(kn[2], kn[3], kb1 + (size_t)(hg + 1) * Tn + v0g + lane);
            }
            const uint32_t rb  = relb + (uint32_t)(((hgl * 32) + (lane ^ hgl)) << 4);
            const uint32_t qb0 = squ + (uint32_t)((((b0 * 16 + hg) * 8) + rh4) << 4);
            const uint32_t qb1 = squ + (uint32_t)((((b1 * 16 + hg) * 8) + rh4) << 4);
#pragma unroll
            for (int r = 0; r < 4; ++r) {
                ull r2a, r2b;
                lds_v2(r2a, r2b, rb + (uint32_t)((((rh4 + r) * 8 * 32)) << 4));
                ull q0a, q0b, q1a, q1b;
                lds_v2(q0a, q0b, qb0 + (uint32_t)(r << 4));
                lds_v2(q1a, q1b, qb1 + (uint32_t)(r << 4));
                s2h[0][r] = fma2(q0a, add2(kc[0], r2a), s2h[0][r]);
                s2h[0][r] = fma2(q0b, add2(kc[1], r2b), s2h[0][r]);
                s2h[1][r] = fma2(q1a, add2(kc[2], r2a), s2h[1][r]);
                s2h[1][r] = fma2(q1b, add2(kc[3], r2b), s2h[1][r]);
            }
#pragma unroll
            for (int i = 0; i < 4; ++i) kc[i] = kn[i];
        }

        if (half == 1) {
            // ---- Phase B: online softmax ----
#pragma unroll
            for (int bi = 0; bi < 2; ++bi) {
                const int bb = b0 + bi;
#pragma unroll
                for (int r = 0; r < 4; ++r) {
                    float xa, xb;
                    unpack2(xa, xb, s2h[bi][r]);
                    float sv = xa + xb;
                    float mt = sv;
#pragma unroll
                    for (int o = 16; o > 0; o >>= 1)
                        mt = fmaxf(mt, __shfl_xor_sync(0xffffffffu, mt, o));
                    float mn = fmaxf(m[bi][r], mt);
                    float sc = __expf(m[bi][r] - mn);
                    float p  = __expf(sv - mn);
                    m[bi][r] = mn;
                    l[bi][r] = l[bi][r] * sc + p;
                    oa2[bi][r] = mul2(oa2[bi][r], pack2(sc, sc));
                    sts_dup(spd + (uint32_t)((((bb * 8 + rh4 + r) * 32) + lane) * 8), p);
                }
            }
            __syncwarp();

            // ---- Phase C: PV, v software-pipelined ----
            ull vc[4], vn[4];
            vc[0] = ldg64(vb0 + (size_t)(v0g)     * HSn + 2 * lane);
            vc[1] = ldg64(vb0 + (size_t)(v0g + 1) * HSn + 2 * lane);
            vc[2] = ldg64(vb1 + (size_t)(v0g)     * HSn + 2 * lane);
            vc[3] = ldg64(vb1 + (size_t)(v0g + 1) * HSn + 2 * lane);
#pragma unroll
            for (int vq = 0; vq < VT; vq += 2) {
                if (vq < VT - 2) {
                    vn[0] = ldg64(vb0 + (size_t)(v0g + vq + 2) * HSn + 2 * lane);
                    vn[1] = ldg64(vb0 + (size_t)(v0g + vq + 3) * HSn + 2 * lane);
                    vn[2] = ldg64(vb1 + (size_t)(v0g + vq + 2) * HSn + 2 * lane);
                    vn[3] = ldg64(vb1 + (size_t)(v0g + vq + 3) * HSn + 2 * lane);
                }
#pragma unroll
                for (int r = 0; r < 4; ++r) {
                    ull p0a, p0b, p1a, p1b;
                    lds_v2(p0a, p0b, spd + (uint32_t)((((b0 * 8 + rh4 + r) * 32) + vq) * 8));
                    lds_v2(p1a, p1b, spd + (uint32_t)((((b1 * 8 + rh4 + r) * 32) + vq) * 8));
                    oa2[0][r] = fma2(p0a, vc[0], oa2[0][r]);
                    oa2[0][r] = fma2(p0b, vc[1], oa2[0][r]);
                    oa2[1][r] = fma2(p1a, vc[2], oa2[1][r]);
                    oa2[1][r] = fma2(p1b, vc[3], oa2[1][r]);
                }
#pragma unroll
                for (int i = 0; i < 4; ++i) vc[i] = vn[i];
            }
            __syncwarp();
        }
    }

    // ---- write unnormalized partials ----
    const int sidx = blockIdx.y;
#pragma unroll
    for (int bi = 0; bi < 2; ++bi) {
        const int bb = b0 + bi;
#pragma unroll
        for (int r = 0; r < 4; ++r) {
            float lt = l[bi][r];
#pragma unroll
            for (int o = 16; o > 0; o >>= 1)
                lt += __shfl_xor_sync(0xffffffffu, lt, o);
            int row = bb * Tn + t0 + rh4 + r;
            float o0, o1;
            unpack2(o0, o1, oa2[bi][r]);
            ((float2*)(g_po[sidx] + (size_t)row * HSn))[lane] = make_float2(o0, o1);
            if (lane == 0) { g_pm[sidx][row] = m[bi][r]; g_pl[sidx][row] = lt; }
        }
    }
}

// ---------------------------------------------------------------------------
// K3: merge SPLIT partials -> normalized output
// ---------------------------------------------------------------------------
__global__ __launch_bounds__(256)
void merge_kernel(float* __restrict__ out)
{
    int idx = blockIdx.x * 256 + threadIdx.x;
    int row = idx >> 6;
    float M = g_pm[0][row];
#pragma unroll
    for (int s = 1; s < SPLIT; ++s) M = fmaxf(M, g_pm[s][row]);
    float denom = 0.f, acc = 0.f;
#pragma unroll
    for (int s = 0; s < SPLIT; ++s) {
        float a = __expf(g_pm[s][row] - M);
        denom += a * g_pl[s][row];
        acc   += a * g_po[s][idx];
    }
    out[idx] = acc / denom;
}

// ---------------------------------------------------------------------------
extern "C" void kernel_launch(void* const* d_in, const int* in_sizes, int n_in,
                              void* d_out, int out_size)
{
    const float* x   = (const float*)d_in[0];
    const float* Wk  = (const float*)d_in[1];
    const float* bk  = (const float*)d_in[2];
    const float* Wq  = (const float*)d_in[3];
    const float* bq  = (const float*)d_in[4];
    const float* Wv  = (const float*)d_in[5];
    const float* bv  = (const float*)d_in[6];
    const float* rel = (const float*)d_in[7];
    float* out = (float*)d_out;

    cudaFuncSetAttribute(attn_kernel,
                         cudaFuncAttributeMaxDynamicSharedMemorySize,
                         ATTN_SMEM_BYTES);

    proj_kernel<<<(Bn * Tn) / 32, 256>>>(x, Wk, bk, Wq, bq, Wv, bv);
    attn_kernel<<<dim3(Tn / TQ, SPLIT), 256, ATTN_SMEM_BYTES>>>(rel);
    merge_kernel<<<(Bn * Tn * HSn) / 256, 256>>>(out);
}

// round 9
// speedup vs baseline: 1.5566x; 1.0197x over previous
#include <cuda_runtime.h>
#include <cstdint>
#include <cstddef>

typedef unsigned long long ull;

#define Bn 8
#define Tn 2048
#define Dn 1024
#define HSn 64
#define TQ 8
#define VT 32
#define SPLIT 8
#define VLEN (Tn / SPLIT)          // 256
#define NTILE (VLEN / VT)          // 8
#define QPT 4                      // h-quarter stages per tile
#define NSTG (NTILE * QPT)         // 32

// Scratch (allocation-free rule: __device__ globals)
__device__ float g_q [(size_t)Bn * Tn * HSn];            // [b][t][h]
__device__ float g_k4[(size_t)Bn * 16 * Tn * 4];         // [b][hg(16)][t][4], pre-scaled by 8
__device__ float g_v [(size_t)Bn * Tn * HSn];            // [b][t][h]
__device__ float g_po[SPLIT][(size_t)Bn * Tn * HSn];
__device__ float g_pm[SPLIT][Bn * Tn];
__device__ float g_pl[SPLIT][Bn * Tn];

// ---- f32x2 + wide-load helpers --------------------------------------------
__device__ __forceinline__ ull pack2(float a, float b) {
    ull r; asm("mov.b64 %0, {%1, %2};" : "=l"(r) : "f"(a), "f"(b)); return r;
}
__device__ __forceinline__ ull add2(ull a, ull b) {
    ull r; asm("add.rn.f32x2 %0, %1, %2;" : "=l"(r) : "l"(a), "l"(b)); return r;
}
__device__ __forceinline__ ull mul2(ull a, ull b) {
    ull r; asm("mul.rn.f32x2 %0, %1, %2;" : "=l"(r) : "l"(a), "l"(b)); return r;
}
__device__ __forceinline__ ull fma2(ull a, ull b, ull c) {
    ull r; asm("fma.rn.f32x2 %0, %1, %2, %3;" : "=l"(r) : "l"(a), "l"(b), "l"(c)); return r;
}
__device__ __forceinline__ void unpack2(float& lo, float& hi, ull v) {
    asm("mov.b64 {%0, %1}, %2;" : "=f"(lo), "=f"(hi) : "l"(v));
}
__device__ __forceinline__ void lds_v2(ull& a, ull& b, uint32_t addr) {
    asm volatile("ld.shared.v2.b64 {%0, %1}, [%2];" : "=l"(a), "=l"(b) : "r"(addr));
}
__device__ __forceinline__ ull ldg64(const void* p) {
    ull r; asm volatile("ld.global.nc.b64 %0, [%1];" : "=l"(r) : "l"(p)); return r;
}
__device__ __forceinline__ void sts_dup(uint32_t addr, float p) {
    asm volatile("st.shared.v2.f32 [%0], {%1, %1};" :: "r"(addr), "f"(p) : "memory");
}
__device__ __forceinline__ void cp_async16(uint32_t dst, const void* src) {
    asm volatile("cp.async.cg.shared.global [%0], [%1], 16;" :: "r"(dst), "l"(src) : "memory");
}

// ---------------------------------------------------------------------------
// K1: fused QKV projection (R5 version — measured best ~306us). FROZEN.
// ---------------------------------------------------------------------------
__global__ __launch_bounds__(256, 3)
void proj_kernel(const float* __restrict__ x,
                 const float* __restrict__ Wk, const float* __restrict__ bk,
                 const float* __restrict__ Wq, const float* __restrict__ bq,
                 const float* __restrict__ Wv, const float* __restrict__ bv)
{
    __shared__ float xsT[64 * 36];     // [k][tok]
    __shared__ float ws[64][193];      // [k][col]

    const int tid  = threadIdx.x;
    const int tok0 = blockIdx.x * 32;
    const int cl   = tid & 31;
    const int tr   = (tid >> 5) << 2;

    const uint32_t xsT_u = (uint32_t)__cvta_generic_to_shared(xsT);

    ull acc2[2][6];
#pragma unroll
    for (int i = 0; i < 2; ++i)
#pragma unroll
        for (int j = 0; j < 6; ++j) acc2[i][j] = 0ull;

    for (int k0 = 0; k0 < Dn; k0 += 64) {
        __syncthreads();
        for (int idx = tid; idx < 32 * 64; idx += 256) {
            int k = idx & 63, tk = idx >> 6;
            xsT[k * 36 + tk] = x[(size_t)(tok0 + tk) * Dn + k0 + k];
        }
        for (int idx = tid; idx < 192 * 64; idx += 256) {
            int k = idx & 63, col = idx >> 6;
            const float* Wsrc = (col < 64) ? Wk : ((col < 128) ? Wq : Wv);
            ws[k][col] = Wsrc[(size_t)(col & 63) * Dn + k0 + k];
        }
        __syncthreads();

#pragma unroll 8
        for (int k = 0; k < 64; ++k) {
            ull x2a, x2b;
            lds_v2(x2a, x2b, xsT_u + (uint32_t)(k * 36 + tr) * 4u);
#pragma unroll
            for (int j = 0; j < 6; ++j) {
                float wv = ws[k][cl + 32 * j];
                ull wd = pack2(wv, wv);
                acc2[0][j] = fma2(x2a, wd, acc2[0][j]);
                acc2[1][j] = fma2(x2b, wd, acc2[1][j]);
            }
        }
    }

#pragma unroll
    for (int j = 0; j < 6; ++j) {
        float a[4];
        unpack2(a[0], a[1], acc2[0][j]);
        unpack2(a[2], a[3], acc2[1][j]);
        int col = cl + 32 * j;
        int h = col & 63;
#pragma unroll
        for (int i = 0; i < 4; ++i) {
            int tokg = tok0 + tr + i;
            int b = tokg >> 11;
            int t = tokg & (Tn - 1);
            if (col < 64) {
                float r = a[i] + bk[h];
                g_k4[(((size_t)(b * 16 + (h >> 2)) * Tn + t) << 2) + (h & 3)] = 8.0f * r;
            } else if (col < 128) {
                g_q[(size_t)tokg * HSn + h] = a[i] + bq[h];
            } else {
                g_v[(size_t)tokg * HSn + h] = a[i] + bv[h];
            }
        }
    }
}

// ---------------------------------------------------------------------------
// K2: fused attention. 256 threads = 8 warps, 2 CTAs/SM.
// Phase A/softmax: warp = (batch-pair b0,b1 = 2*(w&3)) x (row-quad rh4=4*(w>>2)).
// PV:              warp = batch w, rows 0..7 (p + rescale factor via smem).
// rel AND k staged via cp.async in h-quarter ping-pong stages (k L2-read once).
// v read once per CTA (no duplication) thanks to PV reassignment.
// ---------------------------------------------------------------------------
#define RELBUF 16384                 // [tt8][hg4][v32] float4
#define KBUF   16384                 // [hg4][b8][v32] float4
#define K_OFF  (2 * RELBUF)          // 32768
#define Q_OFF  (K_OFF + 2 * KBUF)    // 65536: [b8][hg16][tt8] float4 = 16KB
#define PD_OFF (Q_OFF + 16384)       // 81920: [b8][r8][v32] dup-pair 8B = 16KB
#define SC_OFF (PD_OFF + 16384)      // 98304: [b8][r8] float = 256B
#define ATTN_SMEM_BYTES (SC_OFF + 256)   // 98560

__global__ __launch_bounds__(256, 2)
void attn_kernel(const float* __restrict__ rel)
{
    extern __shared__ float smf[];
    const uint32_t smem0 = (uint32_t)__cvta_generic_to_shared(smf);
    const uint32_t qu    = smem0 + Q_OFF;
    const uint32_t pdu   = smem0 + PD_OFF;

    const int tid  = threadIdx.x;
    const int w    = tid >> 5;
    const int lane = tid & 31;
    const int b0   = (w & 3) * 2;        // phase-A batch pair
    const int b1   = b0 + 1;
    const int rh4  = (w >> 2) << 2;      // phase-A row quad (0 or 4)
    const int t0   = blockIdx.x * TQ;
    const int vbase = blockIdx.y * VLEN;

    // ---- stage q: [b][hg][tt] float4 (published by first stage barrier) ----
    {
        float4* sq4 = (float4*)(smf + (Q_OFF >> 2));
        for (int idx = tid; idx < 1024; idx += 256) {
            int tt = idx & 7, hg = (idx >> 3) & 15, b = idx >> 7;
            sq4[(b * 16 + hg) * 8 + tt] =
                *(const float4*)(g_q + ((size_t)b * Tn + t0 + tt) * HSn + hg * 4);
        }
    }

    // ---- cp.async chunk maps (per stage: rel 16KB + k 16KB = 8 chunks/thr) --
    const float*  srel_c[4];   uint32_t drel_c[4];
    const float4* sk_c[4];     uint32_t dk_c[4];
    const float4* g_k4_f4 = (const float4*)g_k4;
#pragma unroll
    for (int c = 0; c < 4; ++c) {
        int idx = tid + c * 256;                       // 0..1023
        // rel: v fast, then hg(4), then tt(8)
        int rv = idx & 31, rhg = (idx >> 5) & 3, rtt = idx >> 7;
        srel_c[c] = rel + ((size_t)(t0 + rtt) * Tn + vbase + rv) * HSn + rhg * 4;
        drel_c[c] = smem0 + (uint32_t)((((rtt * 4 + rhg) * 32) + rv) << 4);
        // k: v fast, then b(8), then hg(4)
        int kv = idx & 31, kb = (idx >> 5) & 7, khg = idx >> 8;
        sk_c[c] = g_k4_f4 + ((size_t)(kb * 16 + khg) * Tn + vbase + kv);
        dk_c[c] = smem0 + K_OFF + (uint32_t)((((khg * 8 + kb) * 32) + kv) << 4);
    }

    float m[2][4], l[2][4];
#pragma unroll
    for (int bi = 0; bi < 2; ++bi)
#pragma unroll
        for (int r = 0; r < 4; ++r) { m[bi][r] = -1e30f; l[bi][r] = 0.f; }

    ull oa2[8];                                    // PV: batch w, rows 0..7
#pragma unroll
    for (int r = 0; r < 8; ++r) oa2[r] = 0ull;

    const float* vb = g_v + (size_t)w * Tn * HSn;  // PV batch = w

    // prologue: issue stage 0 (tile 0, hq 0)
#pragma unroll
    for (int c = 0; c < 4; ++c) { cp_async16(drel_c[c], srel_c[c]); cp_async16(dk_c[c], sk_c[c]); }
    asm volatile("cp.async.commit_group;" ::: "memory");

    ull s2h[2][4];
    for (int s = 0; s < NSTG; ++s) {
        asm volatile("cp.async.wait_group 0;" ::: "memory");
        __syncthreads();          // publishes stage s; proves stage s-1 reads done

        if (s + 1 < NSTG) {
            int tile1 = (s + 1) >> 2, hq1 = (s + 1) & 3;
            size_t rel_off = (size_t)tile1 * (VT * HSn) + hq1 * 16;         // floats
            size_t k_off   = (size_t)hq1 * 4 * Tn + (size_t)tile1 * VT;      // float4s
            uint32_t bofs  = (uint32_t)(((s + 1) & 1) ? RELBUF : 0);
#pragma unroll
            for (int c = 0; c < 4; ++c) {
                cp_async16(drel_c[c] + bofs, srel_c[c] + rel_off);
                cp_async16(dk_c[c]   + bofs, sk_c[c]   + k_off);
            }
            asm volatile("cp.async.commit_group;" ::: "memory");
        }

        const int tile = s >> 2, hq = s & 3;
        const int v0g  = vbase + tile * VT;
        const uint32_t relb = smem0 + (uint32_t)((s & 1) ? RELBUF : 0);
        const uint32_t kbf  = smem0 + K_OFF + (uint32_t)((s & 1) ? RELBUF : 0);

        if (hq == 0) {
#pragma unroll
            for (int bi = 0; bi < 2; ++bi)
#pragma unroll
                for (int r = 0; r < 4; ++r) s2h[bi][r] = 0ull;
        }

        // ---- Phase A: packed-h scores; k + rel from smem ----
#pragma unroll
        for (int hg = 0; hg < 4; ++hg) {
            ull k0a, k0b, k1a, k1b;
            lds_v2(k0a, k0b, kbf + (uint32_t)((((hg * 8 + b0) * 32) + lane) << 4));
            lds_v2(k1a, k1b, kbf + (uint32_t)((((hg * 8 + b1) * 32) + lane) << 4));
            const int hgg = hq * 4 + hg;
            const uint32_t qb0 = qu + (uint32_t)((((b0 * 16 + hgg) * 8) + rh4) << 4);
            const uint32_t qb1 = qu + (uint32_t)((((b1 * 16 + hgg) * 8) + rh4) << 4);
#pragma unroll
            for (int r = 0; r < 4; ++r) {
                ull r2a, r2b;
                lds_v2(r2a, r2b, relb + (uint32_t)(((((rh4 + r) * 4 + hg) * 32) + lane) << 4));
                ull q0a, q0b, q1a, q1b;
                lds_v2(q0a, q0b, qb0 + (uint32_t)(r << 4));
                lds_v2(q1a, q1b, qb1 + (uint32_t)(r << 4));
                s2h[0][r] = fma2(q0a, add2(k0a, r2a), s2h[0][r]);
                s2h[0][r] = fma2(q0b, add2(k0b, r2b), s2h[0][r]);
                s2h[1][r] = fma2(q1a, add2(k1a, r2a), s2h[1][r]);
                s2h[1][r] = fma2(q1b, add2(k1b, r2b), s2h[1][r]);
            }
        }

        if (hq == QPT - 1) {
            // ---- Phase B: online softmax (warp owns rows for its batch pair) ----
#pragma unroll
            for (int bi = 0; bi < 2; ++bi) {
                const int bb = b0 + bi;
#pragma unroll
                for (int r = 0; r < 4; ++r) {
                    float xa, xb;
                    unpack2(xa, xb, s2h[bi][r]);
                    float sv = xa + xb;
                    float mt = sv;
#pragma unroll
                    for (int o = 16; o > 0; o >>= 1)
                        mt = fmaxf(mt, __shfl_xor_sync(0xffffffffu, mt, o));
                    float mn = fmaxf(m[bi][r], mt);
                    float sc = __expf(m[bi][r] - mn);
                    float p  = __expf(sv - mn);
                    m[bi][r] = mn;
                    l[bi][r] = l[bi][r] * sc + p;
                    sts_dup(pdu + (uint32_t)((((bb * 8 + rh4 + r) * 32) + lane) * 8), p);
                    if (lane == 0) smf[(SC_OFF >> 2) + bb * 8 + rh4 + r] = sc;
                }
            }
            __syncthreads();      // publish p + sc to the PV warps

            // ---- Phase C: PV. Warp = batch w, rows 0..7, v read ONCE per CTA ----
#pragma unroll
            for (int r = 0; r < 8; ++r) {
                float scr = smf[(SC_OFF >> 2) + w * 8 + r];
                oa2[r] = mul2(oa2[r], pack2(scr, scr));
            }
            ull vc0, vc1, vn0, vn1;
            vc0 = ldg64(vb + (size_t)(v0g)     * HSn + 2 * lane);
            vc1 = ldg64(vb + (size_t)(v0g + 1) * HSn + 2 * lane);
#pragma unroll
            for (int vq = 0; vq < VT; vq += 2) {
                if (vq < VT - 2) {
                    vn0 = ldg64(vb + (size_t)(v0g + vq + 2) * HSn + 2 * lane);
                    vn1 = ldg64(vb + (size_t)(v0g + vq + 3) * HSn + 2 * lane);
                }
#pragma unroll
                for (int r = 0; r < 8; ++r) {
                    ull p0, p1;
                    lds_v2(p0, p1, pdu + (uint32_t)((((w * 8 + r) * 32) + vq) * 8));
                    oa2[r] = fma2(p0, vc0, oa2[r]);
                    oa2[r] = fma2(p1, vc1, oa2[r]);
                }
                vc0 = vn0; vc1 = vn1;
            }
        }
    }

    // ---- write unnormalized partials ----
    const int sidx = blockIdx.y;
    // PV warp writes o for (batch w, rows 0..7)
#pragma unroll
    for (int r = 0; r < 8; ++r) {
        int row = w * Tn + t0 + r;
        float o0, o1;
        unpack2(o0, o1, oa2[r]);
        ((float2*)(g_po[sidx] + (size_t)row * HSn))[lane] = make_float2(o0, o1);
    }
    // softmax warp writes (m, l) for its rows
#pragma unroll
    for (int bi = 0; bi < 2; ++bi) {
        const int bb = b0 + bi;
#pragma unroll
        for (int r = 0; r < 4; ++r) {
            float lt = l[bi][r];
#pragma unroll
            for (int o = 16; o > 0; o >>= 1)
                lt += __shfl_xor_sync(0xffffffffu, lt, o);
            if (lane == 0) {
                int row = bb * Tn + t0 + rh4 + r;
                g_pm[sidx][row] = m[bi][r];
                g_pl[sidx][row] = lt;
            }
        }
    }
}

// ---------------------------------------------------------------------------
// K3: merge SPLIT partials -> normalized output
// ---------------------------------------------------------------------------
__global__ __launch_bounds__(256)
void merge_kernel(float* __restrict__ out)
{
    int idx = blockIdx.x * 256 + threadIdx.x;
    int row = idx >> 6;
    float M = g_pm[0][row];
#pragma unroll
    for (int s = 1; s < SPLIT; ++s) M = fmaxf(M, g_pm[s][row]);
    float denom = 0.f, acc = 0.f;
#pragma unroll
    for (int s = 0; s < SPLIT; ++s) {
        float a = __expf(g_pm[s][row] - M);
        denom += a * g_pl[s][row];
        acc   += a * g_po[s][idx];
    }
    out[idx] = acc / denom;
}

// ---------------------------------------------------------------------------
extern "C" void kernel_launch(void* const* d_in, const int* in_sizes, int n_in,
                              void* d_out, int out_size)
{
    const float* x   = (const float*)d_in[0];
    const float* Wk  = (const float*)d_in[1];
    const float* bk  = (const float*)d_in[2];
    const float* Wq  = (const float*)d_in[3];
    const float* bq  = (const float*)d_in[4];
    const float* Wv  = (const float*)d_in[5];
    const float* bv  = (const float*)d_in[6];
    const float* rel = (const float*)d_in[7];
    float* out = (float*)d_out;

    cudaFuncSetAttribute(attn_kernel,
                         cudaFuncAttributeMaxDynamicSharedMemorySize,
                         ATTN_SMEM_BYTES);

    proj_kernel<<<(Bn * Tn) / 32, 256>>>(x, Wk, bk, Wq, bq, Wv, bv);
    attn_kernel<<<dim3(Tn / TQ, SPLIT), 256, ATTN_SMEM_BYTES>>>(rel);
    merge_kernel<<<(Bn * Tn * HSn) / 256, 256>>>(out);
}